// round 8
// baseline (speedup 1.0000x reference)
#include <cuda_runtime.h>
#include <cuda_bf16.h>
#include <math.h>
#include <stdint.h>

// Problem dims (fixed)
#define BB 2
#define SS_ 2048
#define DD 2048
#define HH 16
#define DH_ 128
#define FF_ 8192
#define ROWS 4096            // B*S

// ---------------- scratch ----------------
__device__ float g_h   [(size_t)ROWS * DD];   // h2 (LN2 out, fp32)
__device__ float g_v   [(size_t)ROWS * DD];
__device__ float g_res [(size_t)ROWS * DD];

#define AMAX ((size_t)BB * HH * SS_ * SS_)
#define BMAX ((size_t)DD * FF_)
#define CMAX ((size_t)ROWS * FF_)
__device__ __nv_bfloat16 g_Ah[AMAX];
__device__ __nv_bfloat16 g_Al[AMAX];
__device__ __nv_bfloat16 g_Bh[BMAX];
__device__ __nv_bfloat16 g_Bl[BMAX];
__device__ __nv_bfloat16 g_Ch[CMAX];
__device__ __nv_bfloat16 g_Cl[CMAX];
__device__ __nv_bfloat16 g_Kh[(size_t)ROWS * DD];
__device__ __nv_bfloat16 g_Kl[(size_t)ROWS * DD];

__device__ __forceinline__ uint32_t smem_u32(const void* p) {
    uint32_t a;
    asm("{ .reg .u64 t; cvta.to.shared.u64 t, %1; cvt.u32.u64 %0, t; }" : "=r"(a) : "l"(p));
    return a;
}

#define LDMX4(r0, r1, r2, r3, addr) \
    asm volatile("ldmatrix.sync.aligned.m8n8.x4.shared.b16 {%0,%1,%2,%3}, [%4];" \
                 : "=r"(r0), "=r"(r1), "=r"(r2), "=r"(r3) : "r"(addr))

#define MMA16816(c, a, b0, b1) \
    asm volatile("mma.sync.aligned.m16n8k16.row.col.f32.bf16.bf16.f32 " \
                 "{%0,%1,%2,%3}, {%4,%5,%6,%7}, {%8,%9}, {%0,%1,%2,%3};" \
                 : "+f"((c)[0]), "+f"((c)[1]), "+f"((c)[2]), "+f"((c)[3]) \
                 : "r"((a)[0]), "r"((a)[1]), "r"((a)[2]), "r"((a)[3]), \
                   "r"(b0), "r"(b1))

#define CP16(dst, src) \
    asm volatile("cp.async.cg.shared.global [%0], [%1], 16;" :: "r"(dst), "l"(src))
#define CP_COMMIT() asm volatile("cp.async.commit_group;" ::: "memory")
#define CP_WAIT0()  asm volatile("cp.async.wait_group 0;" ::: "memory")
#define CP_WAIT1()  asm volatile("cp.async.wait_group 1;" ::: "memory")

__device__ __forceinline__ void decomp2_store(__nv_bfloat16* hp, __nv_bfloat16* lp,
                                              long long off, float x, float y) {
    __nv_bfloat16 hx = __float2bfloat16(x);
    __nv_bfloat16 hy = __float2bfloat16(y);
    *(__nv_bfloat162*)(hp + off) = __nv_bfloat162(hx, hy);
    *(__nv_bfloat162*)(lp + off) = __nv_bfloat162(__float2bfloat16(x - __bfloat162float(hx)),
                                                  __float2bfloat16(y - __bfloat162float(hy)));
}

// ===================== LayerNorm fused with bf16 decompose =====================
__global__ void ln_fused_kernel(const float* __restrict__ x,
                                const float* __restrict__ g,
                                const float* __restrict__ b,
                                float* __restrict__ out,          // may be null
                                __nv_bfloat16* __restrict__ oh,
                                __nv_bfloat16* __restrict__ ol) {
    __shared__ float xs[DD];
    __shared__ float red[256];
    const int row = blockIdx.x;
    const int tid = threadIdx.x;
    const float* xr = x + (long long)row * DD;

    float s = 0.f;
    for (int i = tid; i < DD; i += 256) { float t = xr[i]; xs[i] = t; s += t; }
    red[tid] = s; __syncthreads();
    for (int o = 128; o > 0; o >>= 1) { if (tid < o) red[tid] += red[tid + o]; __syncthreads(); }
    const float mean = red[0] * (1.f / DD);
    __syncthreads();

    float v = 0.f;
    for (int i = tid; i < DD; i += 256) { float d = xs[i] - mean; v += d * d; }
    red[tid] = v; __syncthreads();
    for (int o = 128; o > 0; o >>= 1) { if (tid < o) red[tid] += red[tid + o]; __syncthreads(); }
    const float rstd = rsqrtf(red[0] * (1.f / DD) + 1e-5f);

    const long long base = (long long)row * DD;
    for (int i = tid * 2; i < DD; i += 512) {
        float a0 = (xs[i] - mean) * rstd * g[i] + b[i];
        float a1 = (xs[i + 1] - mean) * rstd * g[i + 1] + b[i + 1];
        if (out) *(float2*)(out + base + i) = make_float2(a0, a1);
        decomp2_store(oh, ol, base + i, a0, a1);
    }
}

// ===================== softmax in place + decompose =====================
__global__ void softmax_kernel(float* __restrict__ w,
                               __nv_bfloat16* __restrict__ oh,
                               __nv_bfloat16* __restrict__ ol) {
    __shared__ float sc[SS_];
    __shared__ float red[256];
    const int qi = blockIdx.x, h = blockIdx.y, b = blockIdx.z;
    const int tid = threadIdx.x;
    const long long rbase = ((long long)(b * HH + h) * SS_ + qi) * SS_;
    float* wrow = w + rbase;
    const int n = qi + 1;

    float lmax = -1e30f;
    for (int j = tid; j < n; j += 256) { float t = wrow[j]; sc[j] = t; lmax = fmaxf(lmax, t); }
    red[tid] = lmax; __syncthreads();
    for (int o = 128; o > 0; o >>= 1) { if (tid < o) red[tid] = fmaxf(red[tid], red[tid + o]); __syncthreads(); }
    const float gmax = red[0];
    __syncthreads();

    float lsum = 0.f;
    for (int j = tid; j < n; j += 256) { float e = expf(sc[j] - gmax); sc[j] = e; lsum += e; }
    red[tid] = lsum; __syncthreads();
    for (int o = 128; o > 0; o >>= 1) { if (tid < o) red[tid] += red[tid + o]; __syncthreads(); }
    const float inv = 1.f / red[0];
    __syncthreads();

    for (int j = tid * 2; j < SS_; j += 512) {
        float x = (j < n) ? sc[j] * inv : 0.f;
        float y = (j + 1 < n) ? sc[j + 1] * inv : 0.f;
        *(float2*)(wrow + j) = make_float2(x, y);
        decomp2_store(oh, ol, rbase + j, x, y);
    }
}

// ===================== transpose+decompose weight [K,N] -> [N,K] =====================
__global__ void wtrans_kernel(const float* __restrict__ w,
                              __nv_bfloat16* __restrict__ bh,
                              __nv_bfloat16* __restrict__ bl,
                              int Kdim, int Ndim) {
    __shared__ float t[32][33];
    const int k0 = blockIdx.x * 32, n0 = blockIdx.y * 32;
    const int tx = threadIdx.x & 31, ty = threadIdx.x >> 5;
#pragma unroll
    for (int i = 0; i < 32; i += 8)
        t[ty + i][tx] = w[(long long)(k0 + ty + i) * Ndim + n0 + tx];
    __syncthreads();
#pragma unroll
    for (int i = 0; i < 32; i += 8) {
        float v = t[tx][ty + i];
        long long o = (long long)(n0 + ty + i) * Kdim + k0 + tx;
        __nv_bfloat16 h = __float2bfloat16(v);
        bh[o] = h;
        bl[o] = __float2bfloat16(v - __bfloat162float(h));
    }
}

// ===================== transpose+decompose V [B,S,H,DH] -> [B,H,DH,S] ==========
__global__ void vtrans_kernel(const float* __restrict__ v,
                              __nv_bfloat16* __restrict__ bh,
                              __nv_bfloat16* __restrict__ bl) {
    __shared__ float t[32][33];
    const int bh_i = blockIdx.z;
    const int b = bh_i >> 4, h = bh_i & 15;
    const int s0 = blockIdx.x * 32, d0 = blockIdx.y * 32;
    const int tx = threadIdx.x & 31, ty = threadIdx.x >> 5;
#pragma unroll
    for (int i = 0; i < 32; i += 8)
        t[ty + i][tx] = v[(((long long)b * SS_ + s0 + ty + i) * HH + h) * DH_ + d0 + tx];
    __syncthreads();
#pragma unroll
    for (int i = 0; i < 32; i += 8) {
        float val = t[tx][ty + i];
        long long o = ((long long)bh_i * DH_ + d0 + ty + i) * SS_ + s0 + tx;
        __nv_bfloat16 hh2 = __float2bfloat16(val);
        bh[o] = hh2;
        bl[o] = __float2bfloat16(val - __bfloat162float(hh2));
    }
}

// =======================================================================
// Kernel A: 128x128 tile, 2 CTA/SM GEMM (attention: scores, attn*V)
// =======================================================================
#define SA 40
#define TILEB (128 * SA * 2)
#define STAGEB (4 * TILEB)
#define GSMEM (2 * STAGEB)

__global__ __launch_bounds__(256, 2) void mma_gemm(
        const __nv_bfloat16* __restrict__ Ah, const __nv_bfloat16* __restrict__ Al,
        int lda, long long sAb, long long sAhS,
        const __nv_bfloat16* __restrict__ Bh, const __nv_bfloat16* __restrict__ Bl,
        int ldb, long long sBb, long long sBhS,
        float* __restrict__ C,
        __nv_bfloat16* __restrict__ Oh, __nv_bfloat16* __restrict__ Ol,
        int ldc, long long sCb, long long sCh,
        int K, int Hb, int causal) {
    extern __shared__ char dsm[];

    const int row0 = (causal == 2) ? (int)(gridDim.y - 1 - blockIdx.y) * 128
                                   : (int)blockIdx.y * 128;
    const int col0 = blockIdx.x * 128;
    if (causal == 1 && col0 > row0 + 127) return;

    const int tid = threadIdx.x;
    const int warp = tid >> 5, lane = tid & 31;
    const int wm = warp >> 2, wn = warp & 3;

    const int bz = blockIdx.z;
    const int b = bz / Hb, hh = bz % Hb;
    Ah += b * sAb + hh * sAhS;
    Al += b * sAb + hh * sAhS;
    Bh += b * sBb + hh * sBhS;
    Bl += b * sBb + hh * sBhS;
    const long long cOff = b * sCb + hh * sCh;
    if (C)  C += cOff;
    if (Oh) { Oh += cOff; Ol += cOff; }

    const uint32_t u0 = smem_u32(dsm);

    float acc[4][4][4] = {};

    const int lr0 = tid >> 2, lc = (tid & 3) * 8;
    const int a_r = lane & 15, a_c = (lane >> 4) * 8;
    const int b_r = ((lane >> 4) << 3) + (lane & 7), b_c = ((lane >> 3) & 1) * 8;

    int nch = K / 32;
    if (causal == 2) { int lim = (row0 + 128) / 32; if (lim < nch) nch = lim; }

    auto load_chunk = [&](int ch, int st) {
        const int kb = ch * 32;
        const uint32_t base = u0 + st * STAGEB;
#pragma unroll
        for (int p = 0; p < 2; p++) {
            const int r = lr0 + p * 64;
            const long long ga = (long long)(row0 + r) * lda + kb + lc;
            const long long gb = (long long)(col0 + r) * ldb + kb + lc;
            const uint32_t so = (uint32_t)(r * SA + lc) * 2;
            CP16(base + so,             Ah + ga);
            CP16(base + TILEB + so,     Al + ga);
            CP16(base + 2 * TILEB + so, Bh + gb);
            CP16(base + 3 * TILEB + so, Bl + gb);
        }
    };

    load_chunk(0, 0);
    CP_COMMIT();

    for (int ch = 0; ch < nch; ch++) {
        CP_WAIT0();
        __syncthreads();
        if (ch + 1 < nch) { load_chunk(ch + 1, (ch + 1) & 1); CP_COMMIT(); }

        const uint32_t base = u0 + (ch & 1) * STAGEB;
        const uint32_t uAh = base, uAl = base + TILEB;
        const uint32_t uBh = base + 2 * TILEB, uBl = base + 3 * TILEB;

#pragma unroll
        for (int ks = 0; ks < 2; ks++) {
            const int kc = ks * 16;
            uint32_t af[4][4], fbh[2][4], fbl[2][4];
#pragma unroll
            for (int nb = 0; nb < 2; nb++) {
                const uint32_t off = (uint32_t)((wn * 32 + nb * 16 + b_r) * SA + kc + b_c) * 2;
                LDMX4(fbh[nb][0], fbh[nb][1], fbh[nb][2], fbh[nb][3], uBh + off);
                LDMX4(fbl[nb][0], fbl[nb][1], fbl[nb][2], fbl[nb][3], uBl + off);
            }
#pragma unroll
            for (int mi = 0; mi < 4; mi++) {
                const uint32_t off = (uint32_t)((wm * 64 + mi * 16 + a_r) * SA + kc + a_c) * 2;
                LDMX4(af[mi][0], af[mi][1], af[mi][2], af[mi][3], uAh + off);
            }
#pragma unroll
            for (int mi = 0; mi < 4; mi++)
#pragma unroll
                for (int ni = 0; ni < 4; ni++) {
                    MMA16816(acc[mi][ni], af[mi], fbh[ni >> 1][(ni & 1) * 2], fbh[ni >> 1][(ni & 1) * 2 + 1]);
                    MMA16816(acc[mi][ni], af[mi], fbl[ni >> 1][(ni & 1) * 2], fbl[ni >> 1][(ni & 1) * 2 + 1]);
                }
#pragma unroll
            for (int mi = 0; mi < 4; mi++) {
                const uint32_t off = (uint32_t)((wm * 64 + mi * 16 + a_r) * SA + kc + a_c) * 2;
                LDMX4(af[mi][0], af[mi][1], af[mi][2], af[mi][3], uAl + off);
            }
#pragma unroll
            for (int mi = 0; mi < 4; mi++)
#pragma unroll
                for (int ni = 0; ni < 4; ni++)
                    MMA16816(acc[mi][ni], af[mi], fbh[ni >> 1][(ni & 1) * 2], fbh[ni >> 1][(ni & 1) * 2 + 1]);
        }
    }

#pragma unroll
    for (int mi = 0; mi < 4; mi++) {
#pragma unroll
        for (int ni = 0; ni < 4; ni++) {
#pragma unroll
            for (int half = 0; half < 2; half++) {
                const long long r = row0 + wm * 64 + mi * 16 + (lane >> 2) + half * 8;
                const int cc = col0 + wn * 32 + ni * 8 + (lane & 3) * 2;
                float x = acc[mi][ni][half * 2];
                float y = acc[mi][ni][half * 2 + 1];
                if (C) *(float2*)(C + r * ldc + cc) = make_float2(x, y);
                if (Oh) decomp2_store(Oh, Ol, r * ldc + cc, x, y);
            }
        }
    }
}

// =======================================================================
// Kernel B: 128x256 tile, 64x64 warp tile, 1 CTA, 3-stage (weight GEMMs)
// act: 0 none(fp32 C), 1 gelu->bf16 Oh/Ol, 3 QKV dispatch, 4 fp32 C + res
// =======================================================================
#define WTILEA (128 * SA * 2)     // 10240
#define WTILEB (256 * SA * 2)     // 20480
#define WSTAGE (2 * WTILEA + 2 * WTILEB)   // 61440
#define WSMEM  (3 * WSTAGE)                // 184320

__global__ __launch_bounds__(256, 1) void mma_gemm_w(
        const __nv_bfloat16* __restrict__ Ah, const __nv_bfloat16* __restrict__ Al, int lda,
        const __nv_bfloat16* __restrict__ Bh, const __nv_bfloat16* __restrict__ Bl, int ldb,
        float* __restrict__ C,
        __nv_bfloat16* __restrict__ Oh, __nv_bfloat16* __restrict__ Ol,
        __nv_bfloat16* __restrict__ O2h, __nv_bfloat16* __restrict__ O2l,
        int ldc,
        const float* __restrict__ bias,
        const float* __restrict__ res, int ldr,
        const int* __restrict__ pos,
        int K, int act) {
    extern __shared__ char dsm[];

    const int row0 = blockIdx.y * 128;
    const int col0 = blockIdx.x * 256;

    const int tid = threadIdx.x;
    const int warp = tid >> 5, lane = tid & 31;
    const int wm = warp >> 2, wn = warp & 3;      // wm*64 rows, wn*64 cols

    const uint32_t u0 = smem_u32(dsm);

    float acc[4][8][4] = {};

    const int a_r = lane & 15, a_c = (lane >> 4) * 8;
    const int b_r = ((lane >> 4) << 3) + (lane & 7), b_c = ((lane >> 3) & 1) * 8;

    const int nch = K / 32;

    auto load_chunk = [&](int ch, int st) {
        const int kb = ch * 32;
        const uint32_t base = u0 + st * WSTAGE;
        // A: 128 rows x 4 col-chunks (8 elems)
#pragma unroll
        for (int i = 0; i < 2; i++) {
            const int idx = tid + i * 256;
            const int r = idx >> 2, c = (idx & 3) * 8;
            const long long ga = (long long)(row0 + r) * lda + kb + c;
            const uint32_t so = (uint32_t)(r * SA + c) * 2;
            CP16(base + so,          Ah + ga);
            CP16(base + WTILEA + so, Al + ga);
        }
        // B: 256 rows x 4 col-chunks
#pragma unroll
        for (int i = 0; i < 4; i++) {
            const int idx = tid + i * 256;
            const int r = idx >> 2, c = (idx & 3) * 8;
            const long long gb = (long long)(col0 + r) * ldb + kb + c;
            const uint32_t so = (uint32_t)(r * SA + c) * 2;
            CP16(base + 2 * WTILEA + so,          Bh + gb);
            CP16(base + 2 * WTILEA + WTILEB + so, Bl + gb);
        }
    };

    load_chunk(0, 0); CP_COMMIT();
    if (nch > 1) load_chunk(1, 1);
    CP_COMMIT();

    for (int ch = 0; ch < nch; ch++) {
        CP_WAIT1();
        __syncthreads();
        if (ch + 2 < nch) { load_chunk(ch + 2, (ch + 2) % 3); }
        CP_COMMIT();

        const uint32_t base = u0 + (ch % 3) * WSTAGE;
        const uint32_t uAh = base, uAl = base + WTILEA;
        const uint32_t uBh = base + 2 * WTILEA, uBl = uBh + WTILEB;

#pragma unroll
        for (int ks = 0; ks < 2; ks++) {
            const int kc = ks * 16;
            uint32_t fbh[4][4], fbl[4][4];
#pragma unroll
            for (int nb = 0; nb < 4; nb++) {
                const uint32_t off = (uint32_t)((wn * 64 + nb * 16 + b_r) * SA + kc + b_c) * 2;
                LDMX4(fbh[nb][0], fbh[nb][1], fbh[nb][2], fbh[nb][3], uBh + off);
                LDMX4(fbl[nb][0], fbl[nb][1], fbl[nb][2], fbl[nb][3], uBl + off);
            }
#pragma unroll
            for (int mi = 0; mi < 4; mi++) {
                uint32_t af[4];
                const uint32_t offh = (uint32_t)((wm * 64 + mi * 16 + a_r) * SA + kc + a_c) * 2;
                LDMX4(af[0], af[1], af[2], af[3], uAh + offh);
#pragma unroll
                for (int ni = 0; ni < 8; ni++) {
                    MMA16816(acc[mi][ni], af, fbh[ni >> 1][(ni & 1) * 2], fbh[ni >> 1][(ni & 1) * 2 + 1]);
                    MMA16816(acc[mi][ni], af, fbl[ni >> 1][(ni & 1) * 2], fbl[ni >> 1][(ni & 1) * 2 + 1]);
                }
                LDMX4(af[0], af[1], af[2], af[3], uAl + offh);
#pragma unroll
                for (int ni = 0; ni < 8; ni++)
                    MMA16816(acc[mi][ni], af, fbh[ni >> 1][(ni & 1) * 2], fbh[ni >> 1][(ni & 1) * 2 + 1]);
            }
        }
    }

    // epilogue
    const int sec = col0 >> 11;        // act==3: 0=q, 1=k, 2=v (blocks never straddle)
#pragma unroll
    for (int mi = 0; mi < 4; mi++) {
#pragma unroll
        for (int ni = 0; ni < 8; ni++) {
#pragma unroll
            for (int half = 0; half < 2; half++) {
                const long long r = row0 + wm * 64 + mi * 16 + (lane >> 2) + half * 8;
                const int cc = col0 + wn * 64 + ni * 8 + (lane & 3) * 2;
                float x = acc[mi][ni][half * 2];
                float y = acc[mi][ni][half * 2 + 1];
                if (bias) { x += bias[cc]; y += bias[cc + 1]; }
                if (act == 1) {
                    x = 0.5f * x * (1.f + erff(x * 0.70710678118654752f));
                    y = 0.5f * y * (1.f + erff(y * 0.70710678118654752f));
                } else if (act == 3 && sec < 2) {
                    const int i = (cc & (DH_ - 1)) >> 1;
                    const float ang = (float)pos[r] * exp10f(-(float)i * (1.f / 16.f));
                    const float sn = sinf(ang), cs = cosf(ang);
                    const float nx = x * cs - y * sn;
                    y = y * cs + x * sn;
                    x = nx;
                }
                if (act == 3) {
                    const int ccl = cc & 2047;
                    if (sec == 0)      decomp2_store(Oh,  Ol,  r * DD + ccl, x, y);
                    else if (sec == 1) decomp2_store(O2h, O2l, r * DD + ccl, x, y);
                    else               *(float2*)(C + r * DD + ccl) = make_float2(x, y);
                } else {
                    if (res) { x += res[r * ldr + cc]; y += res[r * ldr + cc + 1]; }
                    if (C) *(float2*)(C + r * ldc + cc) = make_float2(x, y);
                    if (Oh) decomp2_store(Oh, Ol, r * ldc + cc, x, y);
                }
            }
        }
    }
}

// ===================== host launch =====================
extern "C" void kernel_launch(void* const* d_in, const int* in_sizes, int n_in,
                              void* d_out, int out_size) {
    const float* hidden  = (const float*)d_in[0];
    const int*   pos     = (const int*)  d_in[1];
    const float* wq      = (const float*)d_in[2];
    const float* wk      = (const float*)d_in[3];
    const float* wv      = (const float*)d_in[4];
    const float* wo      = (const float*)d_in[5];
    const float* ln1_g   = (const float*)d_in[6];
    const float* ln1_b   = (const float*)d_in[7];
    const float* ln2_g   = (const float*)d_in[8];
    const float* ln2_b   = (const float*)d_in[9];
    const float* fc_in_w = (const float*)d_in[10];
    const float* fc_in_b = (const float*)d_in[11];
    const float* fc_out_w= (const float*)d_in[12];
    const float* fc_out_b= (const float*)d_in[13];

    float* out0 = (float*)d_out;                               // [B,S,D]
    float* out1 = out0 + (long long)BB * SS_ * DD;             // [B,H,S,S]

    float *h, *v, *res;
    __nv_bfloat16 *Ah, *Al, *Bh, *Bl, *Ch, *Cl, *Kh, *Kl;
    cudaGetSymbolAddress((void**)&h,   g_h);
    cudaGetSymbolAddress((void**)&v,   g_v);
    cudaGetSymbolAddress((void**)&res, g_res);
    cudaGetSymbolAddress((void**)&Ah,  g_Ah);
    cudaGetSymbolAddress((void**)&Al,  g_Al);
    cudaGetSymbolAddress((void**)&Bh,  g_Bh);
    cudaGetSymbolAddress((void**)&Bl,  g_Bl);
    cudaGetSymbolAddress((void**)&Ch,  g_Ch);
    cudaGetSymbolAddress((void**)&Cl,  g_Cl);
    cudaGetSymbolAddress((void**)&Kh,  g_Kh);
    cudaGetSymbolAddress((void**)&Kl,  g_Kl);

    cudaFuncSetAttribute(mma_gemm,   cudaFuncAttributeMaxDynamicSharedMemorySize, GSMEM);
    cudaFuncSetAttribute(mma_gemm_w, cudaFuncAttributeMaxDynamicSharedMemorySize, WSMEM);

    // 1. LN1 -> bf16 hi/lo only
    ln_fused_kernel<<<ROWS, 256>>>(hidden, ln1_g, ln1_b, nullptr, Ah, Al);

    // 2. merged QKV: B = [wq^T | wk^T | wv^T] (6144 x 2048)
    dim3 gW(DD / 32, DD / 32);
    wtrans_kernel<<<gW, 256>>>(wq, Bh,                   Bl,                   DD, DD);
    wtrans_kernel<<<gW, 256>>>(wk, Bh + (size_t)DD*DD,   Bl + (size_t)DD*DD,   DD, DD);
    wtrans_kernel<<<gW, 256>>>(wv, Bh + (size_t)2*DD*DD, Bl + (size_t)2*DD*DD, DD, DD);
    {
        dim3 g(3 * DD / 256, ROWS / 128);
        mma_gemm_w<<<g, 256, WSMEM>>>(Ah, Al, DD, Bh, Bl, DD,
                                      v, Ch, Cl, Kh, Kl, DD,
                                      nullptr, nullptr, 0, pos, DD, 3);
    }

    // 3. scores = q @ k^T (causal blocks) -> out1 fp32
    {
        dim3 gS(SS_ / 128, SS_ / 128, BB * HH);
        mma_gemm<<<gS, 256, GSMEM>>>(
            Ch, Cl, DD, (long long)SS_ * DD, DH_,
            Kh, Kl, DD, (long long)SS_ * DD, DH_,
            out1, nullptr, nullptr,
            SS_, (long long)HH * SS_ * SS_, (long long)SS_ * SS_,
            DH_, HH, 1);
    }

    // 4. softmax in place + decompose -> Ah/Al
    {
        dim3 gA(SS_, HH, BB);
        softmax_kernel<<<gA, 256>>>(out1, Ah, Al);
    }

    // 5. v^T decompose -> Bh/Bl; ctx = weights @ v (bf16 hi/lo -> Ch/Cl)
    {
        dim3 gVT(SS_ / 32, DH_ / 32, BB * HH);
        vtrans_kernel<<<gVT, 256>>>(v, Bh, Bl);
        dim3 gV(DH_ / 128, SS_ / 128, BB * HH);
        mma_gemm<<<gV, 256, GSMEM>>>(
            Ah, Al, SS_, (long long)HH * SS_ * SS_, (long long)SS_ * SS_,
            Bh, Bl, SS_, (long long)HH * DH_ * SS_, (long long)DH_ * SS_,
            nullptr, Ch, Cl, DD, (long long)SS_ * DD, DH_,
            SS_, HH, 2);
    }

    // 6. res = ctx @ wo + hidden (fp32)
    wtrans_kernel<<<gW, 256>>>(wo, Bh, Bl, DD, DD);
    {
        dim3 g(DD / 256, ROWS / 128);
        mma_gemm_w<<<g, 256, WSMEM>>>(Ch, Cl, DD, Bh, Bl, DD,
                                      res, nullptr, nullptr, nullptr, nullptr, DD,
                                      nullptr, hidden, DD, nullptr, DD, 4);
    }

    // 7. LN2 -> h fp32 + Ah/Al
    ln_fused_kernel<<<ROWS, 256>>>(res, ln2_g, ln2_b, h, Ah, Al);

    // 8. ffn = gelu(h2 @ fc_in + b) -> bf16 hi/lo Ch/Cl
    {
        dim3 gW1(DD / 32, FF_ / 32);
        wtrans_kernel<<<gW1, 256>>>(fc_in_w, Bh, Bl, DD, FF_);
        dim3 g(FF_ / 256, ROWS / 128);
        mma_gemm_w<<<g, 256, WSMEM>>>(Ah, Al, DD, Bh, Bl, DD,
                                      nullptr, Ch, Cl, nullptr, nullptr, FF_,
                                      fc_in_b, nullptr, 0, nullptr, DD, 1);
    }

    // 9. out0 = ffn @ fc_out + b + h2
    {
        dim3 gW2(FF_ / 32, DD / 32);
        wtrans_kernel<<<gW2, 256>>>(fc_out_w, Bh, Bl, FF_, DD);
        dim3 g(DD / 256, ROWS / 128);
        mma_gemm_w<<<g, 256, WSMEM>>>(Ch, Cl, FF_, Bh, Bl, FF_,
                                      out0, nullptr, nullptr, nullptr, nullptr, DD,
                                      fc_out_b, h, DD, nullptr, FF_, 4);
    }
}

// round 9
// speedup vs baseline: 1.0599x; 1.0599x over previous
#include <cuda_runtime.h>
#include <cuda_bf16.h>
#include <math.h>
#include <stdint.h>

// Problem dims (fixed)
#define BB 2
#define SS_ 2048
#define DD 2048
#define HH 16
#define DH_ 128
#define FF_ 8192
#define ROWS 4096            // B*S

// ---------------- scratch ----------------
__device__ float g_h   [(size_t)ROWS * DD];   // h2 (LN2 out, fp32)
__device__ float g_v   [(size_t)ROWS * DD];
__device__ float g_res [(size_t)ROWS * DD];

#define AMAX ((size_t)BB * HH * SS_ * SS_)
#define BMAX ((size_t)DD * FF_)
#define CMAX ((size_t)ROWS * FF_)
__device__ __nv_bfloat16 g_Ah[AMAX];
__device__ __nv_bfloat16 g_Al[AMAX];
__device__ __nv_bfloat16 g_Bh[BMAX];
__device__ __nv_bfloat16 g_Bl[BMAX];
__device__ __nv_bfloat16 g_Ch[CMAX];
__device__ __nv_bfloat16 g_Cl[CMAX];
__device__ __nv_bfloat16 g_Kh[(size_t)ROWS * DD];
__device__ __nv_bfloat16 g_Kl[(size_t)ROWS * DD];

__device__ __forceinline__ uint32_t smem_u32(const void* p) {
    uint32_t a;
    asm("{ .reg .u64 t; cvta.to.shared.u64 t, %1; cvt.u32.u64 %0, t; }" : "=r"(a) : "l"(p));
    return a;
}

#define LDMX4(r0, r1, r2, r3, addr) \
    asm volatile("ldmatrix.sync.aligned.m8n8.x4.shared.b16 {%0,%1,%2,%3}, [%4];" \
                 : "=r"(r0), "=r"(r1), "=r"(r2), "=r"(r3) : "r"(addr))

#define MMA16816(c, a, b0, b1) \
    asm volatile("mma.sync.aligned.m16n8k16.row.col.f32.bf16.bf16.f32 " \
                 "{%0,%1,%2,%3}, {%4,%5,%6,%7}, {%8,%9}, {%0,%1,%2,%3};" \
                 : "+f"((c)[0]), "+f"((c)[1]), "+f"((c)[2]), "+f"((c)[3]) \
                 : "r"((a)[0]), "r"((a)[1]), "r"((a)[2]), "r"((a)[3]), \
                   "r"(b0), "r"(b1))

#define CP16(dst, src) \
    asm volatile("cp.async.cg.shared.global [%0], [%1], 16;" :: "r"(dst), "l"(src))
#define CP_COMMIT() asm volatile("cp.async.commit_group;" ::: "memory")
#define CP_WAIT0()  asm volatile("cp.async.wait_group 0;" ::: "memory")

__device__ __forceinline__ void decomp2_store(__nv_bfloat16* hp, __nv_bfloat16* lp,
                                              long long off, float x, float y) {
    __nv_bfloat16 hx = __float2bfloat16(x);
    __nv_bfloat16 hy = __float2bfloat16(y);
    *(__nv_bfloat162*)(hp + off) = __nv_bfloat162(hx, hy);
    *(__nv_bfloat162*)(lp + off) = __nv_bfloat162(__float2bfloat16(x - __bfloat162float(hx)),
                                                  __float2bfloat16(y - __bfloat162float(hy)));
}

// ===================== LayerNorm fused with bf16 decompose =====================
__global__ void ln_fused_kernel(const float* __restrict__ x,
                                const float* __restrict__ g,
                                const float* __restrict__ b,
                                float* __restrict__ out,          // may be null
                                __nv_bfloat16* __restrict__ oh,
                                __nv_bfloat16* __restrict__ ol) {
    __shared__ float xs[DD];
    __shared__ float red[256];
    const int row = blockIdx.x;
    const int tid = threadIdx.x;
    const float* xr = x + (long long)row * DD;

    float s = 0.f;
    for (int i = tid; i < DD; i += 256) { float t = xr[i]; xs[i] = t; s += t; }
    red[tid] = s; __syncthreads();
    for (int o = 128; o > 0; o >>= 1) { if (tid < o) red[tid] += red[tid + o]; __syncthreads(); }
    const float mean = red[0] * (1.f / DD);
    __syncthreads();

    float v = 0.f;
    for (int i = tid; i < DD; i += 256) { float d = xs[i] - mean; v += d * d; }
    red[tid] = v; __syncthreads();
    for (int o = 128; o > 0; o >>= 1) { if (tid < o) red[tid] += red[tid + o]; __syncthreads(); }
    const float rstd = rsqrtf(red[0] * (1.f / DD) + 1e-5f);

    const long long base = (long long)row * DD;
    for (int i = tid * 2; i < DD; i += 512) {
        float a0 = (xs[i] - mean) * rstd * g[i] + b[i];
        float a1 = (xs[i + 1] - mean) * rstd * g[i + 1] + b[i + 1];
        if (out) *(float2*)(out + base + i) = make_float2(a0, a1);
        decomp2_store(oh, ol, base + i, a0, a1);
    }
}

// ===================== softmax in place + decompose =====================
__global__ void softmax_kernel(float* __restrict__ w,
                               __nv_bfloat16* __restrict__ oh,
                               __nv_bfloat16* __restrict__ ol) {
    __shared__ float sc[SS_];
    __shared__ float red[256];
    const int qi = blockIdx.x, h = blockIdx.y, b = blockIdx.z;
    const int tid = threadIdx.x;
    const long long rbase = ((long long)(b * HH + h) * SS_ + qi) * SS_;
    float* wrow = w + rbase;
    const int n = qi + 1;

    float lmax = -1e30f;
    for (int j = tid; j < n; j += 256) { float t = wrow[j]; sc[j] = t; lmax = fmaxf(lmax, t); }
    red[tid] = lmax; __syncthreads();
    for (int o = 128; o > 0; o >>= 1) { if (tid < o) red[tid] = fmaxf(red[tid], red[tid + o]); __syncthreads(); }
    const float gmax = red[0];
    __syncthreads();

    float lsum = 0.f;
    for (int j = tid; j < n; j += 256) { float e = expf(sc[j] - gmax); sc[j] = e; lsum += e; }
    red[tid] = lsum; __syncthreads();
    for (int o = 128; o > 0; o >>= 1) { if (tid < o) red[tid] += red[tid + o]; __syncthreads(); }
    const float inv = 1.f / red[0];
    __syncthreads();

    for (int j = tid * 2; j < SS_; j += 512) {
        float x = (j < n) ? sc[j] * inv : 0.f;
        float y = (j + 1 < n) ? sc[j + 1] * inv : 0.f;
        *(float2*)(wrow + j) = make_float2(x, y);
        decomp2_store(oh, ol, rbase + j, x, y);
    }
}

// ===================== transpose+decompose weight [K,N] -> [N,K] =====================
__global__ void wtrans_kernel(const float* __restrict__ w,
                              __nv_bfloat16* __restrict__ bh,
                              __nv_bfloat16* __restrict__ bl,
                              int Kdim, int Ndim) {
    __shared__ float t[32][33];
    const int k0 = blockIdx.x * 32, n0 = blockIdx.y * 32;
    const int tx = threadIdx.x & 31, ty = threadIdx.x >> 5;
#pragma unroll
    for (int i = 0; i < 32; i += 8)
        t[ty + i][tx] = w[(long long)(k0 + ty + i) * Ndim + n0 + tx];
    __syncthreads();
#pragma unroll
    for (int i = 0; i < 32; i += 8) {
        float v = t[tx][ty + i];
        long long o = (long long)(n0 + ty + i) * Kdim + k0 + tx;
        __nv_bfloat16 h = __float2bfloat16(v);
        bh[o] = h;
        bl[o] = __float2bfloat16(v - __bfloat162float(h));
    }
}

// ===================== transpose+decompose V [B,S,H,DH] -> [B,H,DH,S] ==========
__global__ void vtrans_kernel(const float* __restrict__ v,
                              __nv_bfloat16* __restrict__ bh,
                              __nv_bfloat16* __restrict__ bl) {
    __shared__ float t[32][33];
    const int bh_i = blockIdx.z;
    const int b = bh_i >> 4, h = bh_i & 15;
    const int s0 = blockIdx.x * 32, d0 = blockIdx.y * 32;
    const int tx = threadIdx.x & 31, ty = threadIdx.x >> 5;
#pragma unroll
    for (int i = 0; i < 32; i += 8)
        t[ty + i][tx] = v[(((long long)b * SS_ + s0 + ty + i) * HH + h) * DH_ + d0 + tx];
    __syncthreads();
#pragma unroll
    for (int i = 0; i < 32; i += 8) {
        float val = t[tx][ty + i];
        long long o = ((long long)bh_i * DH_ + d0 + ty + i) * SS_ + s0 + tx;
        __nv_bfloat16 hh2 = __float2bfloat16(val);
        bh[o] = hh2;
        bl[o] = __float2bfloat16(val - __bfloat162float(hh2));
    }
}

// ===================== pipelined mma.sync bf16x3 GEMM =====================
// 128x128 CTA tile, BK=32, 2-stage, 2 CTA/SM; 4 warps (128 thr), 64x64 warp tile.
// out = act( A @ B^T + bias ) [+ res]; A[M,K], B[N,K] hi/lo bf16 K-major
// act: 0 none, 1 gelu, 2 rope->Oh/Ol
// causal: 0 none, 1 skip blocks col0>row0+127, 2 limit K to row0+128
#define SA 40
#define TILEB (128 * SA * 2)
#define STAGEB (4 * TILEB)
#define GSMEM (2 * STAGEB)

__global__ __launch_bounds__(128, 2) void mma_gemm(
        const __nv_bfloat16* __restrict__ Ah, const __nv_bfloat16* __restrict__ Al,
        int lda, long long sAb, long long sAhS,
        const __nv_bfloat16* __restrict__ Bh, const __nv_bfloat16* __restrict__ Bl,
        int ldb, long long sBb, long long sBhS,
        float* __restrict__ C,
        __nv_bfloat16* __restrict__ Oh, __nv_bfloat16* __restrict__ Ol,
        int ldc, long long sCb, long long sCh,
        const float* __restrict__ bias,
        const float* __restrict__ res, int ldr, long long sRb, long long sRh,
        const int* __restrict__ pos,
        int K, int Hb, int act, int causal) {
    extern __shared__ char dsm[];

    const int row0 = blockIdx.y * 128;
    const int col0 = blockIdx.x * 128;
    if (causal == 1 && col0 > row0 + 127) return;

    const int tid = threadIdx.x;
    const int warp = tid >> 5, lane = tid & 31;
    const int wm = warp >> 1, wn = warp & 1;      // 2x2 warps, 64x64 each

    const int bz = blockIdx.z;
    const int b = bz / Hb, hh = bz % Hb;
    Ah += b * sAb + hh * sAhS;
    Al += b * sAb + hh * sAhS;
    Bh += b * sBb + hh * sBhS;
    Bl += b * sBb + hh * sBhS;
    const long long cOff = b * sCb + hh * sCh;
    if (C)  C += cOff;
    if (Oh) { Oh += cOff; Ol += cOff; }
    if (res) res += b * sRb + hh * sRh;

    const uint32_t u0 = smem_u32(dsm);

    float acc[4][8][4] = {};

    const int lr0 = tid >> 2, lc = (tid & 3) * 8;   // 32 rows x 4 chunks per pass
    const int a_r = lane & 15, a_c = (lane >> 4) * 8;
    const int b_r = ((lane >> 4) << 3) + (lane & 7), b_c = ((lane >> 3) & 1) * 8;

    int nch = K / 32;
    if (causal == 2) { int lim = (row0 + 128) / 32; if (lim < nch) nch = lim; }

    auto load_chunk = [&](int ch, int st) {
        const int kb = ch * 32;
        const uint32_t base = u0 + st * STAGEB;
#pragma unroll
        for (int p = 0; p < 4; p++) {
            const int r = lr0 + p * 32;
            const long long ga = (long long)(row0 + r) * lda + kb + lc;
            const long long gb = (long long)(col0 + r) * ldb + kb + lc;
            const uint32_t so = (uint32_t)(r * SA + lc) * 2;
            CP16(base + so,             Ah + ga);
            CP16(base + TILEB + so,     Al + ga);
            CP16(base + 2 * TILEB + so, Bh + gb);
            CP16(base + 3 * TILEB + so, Bl + gb);
        }
    };

    load_chunk(0, 0);
    CP_COMMIT();

    for (int ch = 0; ch < nch; ch++) {
        CP_WAIT0();
        __syncthreads();
        if (ch + 1 < nch) { load_chunk(ch + 1, (ch + 1) & 1); CP_COMMIT(); }

        const uint32_t base = u0 + (ch & 1) * STAGEB;
        const uint32_t uAh = base, uAl = base + TILEB;
        const uint32_t uBh = base + 2 * TILEB, uBl = base + 3 * TILEB;

#pragma unroll
        for (int ks = 0; ks < 2; ks++) {
            const int kc = ks * 16;
            uint32_t fbh[4][4], fbl[4][4];
#pragma unroll
            for (int nb = 0; nb < 4; nb++) {
                const uint32_t off = (uint32_t)((wn * 64 + nb * 16 + b_r) * SA + kc + b_c) * 2;
                LDMX4(fbh[nb][0], fbh[nb][1], fbh[nb][2], fbh[nb][3], uBh + off);
                LDMX4(fbl[nb][0], fbl[nb][1], fbl[nb][2], fbl[nb][3], uBl + off);
            }
#pragma unroll
            for (int mi = 0; mi < 4; mi++) {
                uint32_t af[4];
                const uint32_t offh = (uint32_t)((wm * 64 + mi * 16 + a_r) * SA + kc + a_c) * 2;
                LDMX4(af[0], af[1], af[2], af[3], uAh + offh);
#pragma unroll
                for (int ni = 0; ni < 8; ni++) {
                    MMA16816(acc[mi][ni], af, fbh[ni >> 1][(ni & 1) * 2], fbh[ni >> 1][(ni & 1) * 2 + 1]);
                    MMA16816(acc[mi][ni], af, fbl[ni >> 1][(ni & 1) * 2], fbl[ni >> 1][(ni & 1) * 2 + 1]);
                }
                LDMX4(af[0], af[1], af[2], af[3], uAl + offh);
#pragma unroll
                for (int ni = 0; ni < 8; ni++)
                    MMA16816(acc[mi][ni], af, fbh[ni >> 1][(ni & 1) * 2], fbh[ni >> 1][(ni & 1) * 2 + 1]);
            }
        }
        __syncthreads();
    }

    // epilogue
#pragma unroll
    for (int mi = 0; mi < 4; mi++) {
#pragma unroll
        for (int ni = 0; ni < 8; ni++) {
#pragma unroll
            for (int half = 0; half < 2; half++) {
                const long long r = row0 + wm * 64 + mi * 16 + (lane >> 2) + half * 8;
                const int cc = col0 + wn * 64 + ni * 8 + (lane & 3) * 2;
                float x = acc[mi][ni][half * 2];
                float y = acc[mi][ni][half * 2 + 1];
                if (bias) { x += bias[cc]; y += bias[cc + 1]; }
                if (act == 1) {
                    x = 0.5f * x * (1.f + erff(x * 0.70710678118654752f));
                    y = 0.5f * y * (1.f + erff(y * 0.70710678118654752f));
                } else if (act == 2) {
                    const int i = (cc & (DH_ - 1)) >> 1;
                    const float ang = (float)pos[r] * exp10f(-(float)i * (1.f / 16.f));
                    const float sn = sinf(ang), cs = cosf(ang);
                    const float nx = x * cs - y * sn;
                    y = y * cs + x * sn;
                    x = nx;
                }
                if (res) {
                    x += res[r * ldr + cc];
                    y += res[r * ldr + cc + 1];
                }
                if (C) *(float2*)(C + r * ldc + cc) = make_float2(x, y);
                if (Oh) decomp2_store(Oh, Ol, r * ldc + cc, x, y);
            }
        }
    }
}

// ===================== host launch =====================
extern "C" void kernel_launch(void* const* d_in, const int* in_sizes, int n_in,
                              void* d_out, int out_size) {
    const float* hidden  = (const float*)d_in[0];
    const int*   pos     = (const int*)  d_in[1];
    const float* wq      = (const float*)d_in[2];
    const float* wk      = (const float*)d_in[3];
    const float* wv      = (const float*)d_in[4];
    const float* wo      = (const float*)d_in[5];
    const float* ln1_g   = (const float*)d_in[6];
    const float* ln1_b   = (const float*)d_in[7];
    const float* ln2_g   = (const float*)d_in[8];
    const float* ln2_b   = (const float*)d_in[9];
    const float* fc_in_w = (const float*)d_in[10];
    const float* fc_in_b = (const float*)d_in[11];
    const float* fc_out_w= (const float*)d_in[12];
    const float* fc_out_b= (const float*)d_in[13];

    float* out0 = (float*)d_out;                               // [B,S,D]
    float* out1 = out0 + (long long)BB * SS_ * DD;             // [B,H,S,S]

    float *h, *v, *res;
    __nv_bfloat16 *Ah, *Al, *Bh, *Bl, *Ch, *Cl, *Kh, *Kl;
    cudaGetSymbolAddress((void**)&h,   g_h);
    cudaGetSymbolAddress((void**)&v,   g_v);
    cudaGetSymbolAddress((void**)&res, g_res);
    cudaGetSymbolAddress((void**)&Ah,  g_Ah);
    cudaGetSymbolAddress((void**)&Al,  g_Al);
    cudaGetSymbolAddress((void**)&Bh,  g_Bh);
    cudaGetSymbolAddress((void**)&Bl,  g_Bl);
    cudaGetSymbolAddress((void**)&Ch,  g_Ch);
    cudaGetSymbolAddress((void**)&Cl,  g_Cl);
    cudaGetSymbolAddress((void**)&Kh,  g_Kh);
    cudaGetSymbolAddress((void**)&Kl,  g_Kl);

    cudaFuncSetAttribute(mma_gemm, cudaFuncAttributeMaxDynamicSharedMemorySize, GSMEM);

    // 1. LN1 -> bf16 hi/lo only
    ln_fused_kernel<<<ROWS, 256>>>(hidden, ln1_g, ln1_b, nullptr, Ah, Al);

    // 2. QKV. q,k fuse RoPE in epilogue and emit hi/lo directly; v stays fp32.
    dim3 gQ(DD / 128, ROWS / 128, 1);
    dim3 gW(DD / 32, DD / 32);
    wtrans_kernel<<<gW, 256>>>(wq, Bh, Bl, DD, DD);
    mma_gemm<<<gQ, 128, GSMEM>>>(Ah, Al, DD, 0, 0, Bh, Bl, DD, 0, 0,
                                 nullptr, Ch, Cl, DD, 0, 0,
                                 nullptr, nullptr, 0, 0, 0, pos, DD, 1, 2, 0);
    wtrans_kernel<<<gW, 256>>>(wk, Bh, Bl, DD, DD);
    mma_gemm<<<gQ, 128, GSMEM>>>(Ah, Al, DD, 0, 0, Bh, Bl, DD, 0, 0,
                                 nullptr, Kh, Kl, DD, 0, 0,
                                 nullptr, nullptr, 0, 0, 0, pos, DD, 1, 2, 0);
    wtrans_kernel<<<gW, 256>>>(wv, Bh, Bl, DD, DD);
    mma_gemm<<<gQ, 128, GSMEM>>>(Ah, Al, DD, 0, 0, Bh, Bl, DD, 0, 0,
                                 v, nullptr, nullptr, DD, 0, 0,
                                 nullptr, nullptr, 0, 0, 0, nullptr, DD, 1, 0, 0);

    // 3. scores = q @ k^T (causal blocks) -> out1 fp32
    {
        dim3 gS(SS_ / 128, SS_ / 128, BB * HH);
        mma_gemm<<<gS, 128, GSMEM>>>(
            Ch, Cl, DD, (long long)SS_ * DD, DH_,
            Kh, Kl, DD, (long long)SS_ * DD, DH_,
            out1, nullptr, nullptr, SS_, (long long)HH * SS_ * SS_, (long long)SS_ * SS_,
            nullptr, nullptr, 0, 0, 0, nullptr, DH_, HH, 0, 1);
    }

    // 4. softmax in place + decompose -> Ah/Al
    {
        dim3 gA(SS_, HH, BB);
        softmax_kernel<<<gA, 256>>>(out1, Ah, Al);
    }

    // 5. v^T decompose -> Bh/Bl; ctx = weights @ v (bf16 hi/lo -> Ch/Cl)
    {
        dim3 gVT(SS_ / 32, DH_ / 32, BB * HH);
        vtrans_kernel<<<gVT, 256>>>(v, Bh, Bl);
        dim3 gV(DH_ / 128, SS_ / 128, BB * HH);
        mma_gemm<<<gV, 128, GSMEM>>>(
            Ah, Al, SS_, (long long)HH * SS_ * SS_, (long long)SS_ * SS_,
            Bh, Bl, SS_, (long long)HH * DH_ * SS_, (long long)DH_ * SS_,
            nullptr, Ch, Cl, DD, (long long)SS_ * DD, DH_,
            nullptr, nullptr, 0, 0, 0, nullptr, SS_, HH, 0, 2);
    }

    // 6. res = ctx @ wo + hidden (fp32)
    wtrans_kernel<<<gW, 256>>>(wo, Bh, Bl, DD, DD);
    mma_gemm<<<gQ, 128, GSMEM>>>(Ch, Cl, DD, 0, 0, Bh, Bl, DD, 0, 0,
                                 res, nullptr, nullptr, DD, 0, 0,
                                 nullptr, hidden, DD, 0, 0, nullptr, DD, 1, 0, 0);

    // 7. LN2 -> h fp32 + Ah/Al
    ln_fused_kernel<<<ROWS, 256>>>(res, ln2_g, ln2_b, h, Ah, Al);

    // 8. ffn = gelu(h2 @ fc_in + b) -> bf16 hi/lo Ch/Cl
    {
        dim3 gW1(DD / 32, FF_ / 32);
        wtrans_kernel<<<gW1, 256>>>(fc_in_w, Bh, Bl, DD, FF_);
        dim3 gF1(FF_ / 128, ROWS / 128, 1);
        mma_gemm<<<gF1, 128, GSMEM>>>(Ah, Al, DD, 0, 0, Bh, Bl, DD, 0, 0,
                                      nullptr, Ch, Cl, FF_, 0, 0,
                                      fc_in_b, nullptr, 0, 0, 0, nullptr, DD, 1, 1, 0);
    }

    // 9. out0 = ffn @ fc_out + b + h2
    {
        dim3 gW2(FF_ / 32, DD / 32);
        wtrans_kernel<<<gW2, 256>>>(fc_out_w, Bh, Bl, FF_, DD);
        dim3 gF2(DD / 128, ROWS / 128, 1);
        mma_gemm<<<gF2, 128, GSMEM>>>(Ch, Cl, FF_, 0, 0, Bh, Bl, FF_, 0, 0,
                                      out0, nullptr, nullptr, DD, 0, 0,
                                      fc_out_b, h, DD, 0, 0, nullptr, FF_, 1, 0, 0);
    }
}

// round 10
// speedup vs baseline: 1.3012x; 1.2276x over previous
#include <cuda_runtime.h>
#include <cuda_bf16.h>
#include <cuda_fp16.h>
#include <math.h>
#include <stdint.h>

// Problem dims (fixed)
#define BB 2
#define SS_ 2048
#define DD 2048
#define HH 16
#define DH_ 128
#define FF_ 8192
#define ROWS 4096            // B*S

// ---------------- scratch ----------------
__device__ float g_h   [(size_t)ROWS * DD];   // h2 (LN2 out, fp32)
__device__ float g_v   [(size_t)ROWS * DD];
__device__ float g_res [(size_t)ROWS * DD];

#define AMAX ((size_t)BB * HH * SS_ * SS_)
#define BMAX ((size_t)DD * FF_)
#define CMAX ((size_t)ROWS * FF_)
__device__ __nv_bfloat16 g_Ah[AMAX];
__device__ __nv_bfloat16 g_Al[AMAX];
__device__ __nv_bfloat16 g_Bh[BMAX];
__device__ __nv_bfloat16 g_Bl[BMAX];
__device__ __nv_bfloat16 g_Ch[CMAX];
__device__ __nv_bfloat16 g_Cl[CMAX];
__device__ __nv_bfloat16 g_Kh[(size_t)ROWS * DD];
__device__ __nv_bfloat16 g_Kl[(size_t)ROWS * DD];

__device__ __forceinline__ uint32_t smem_u32(const void* p) {
    uint32_t a;
    asm("{ .reg .u64 t; cvta.to.shared.u64 t, %1; cvt.u32.u64 %0, t; }" : "=r"(a) : "l"(p));
    return a;
}

#define LDMX4(r0, r1, r2, r3, addr) \
    asm volatile("ldmatrix.sync.aligned.m8n8.x4.shared.b16 {%0,%1,%2,%3}, [%4];" \
                 : "=r"(r0), "=r"(r1), "=r"(r2), "=r"(r3) : "r"(addr))

#define MMA16816(c, a, b0, b1) \
    asm volatile("mma.sync.aligned.m16n8k16.row.col.f32.bf16.bf16.f32 " \
                 "{%0,%1,%2,%3}, {%4,%5,%6,%7}, {%8,%9}, {%0,%1,%2,%3};" \
                 : "+f"((c)[0]), "+f"((c)[1]), "+f"((c)[2]), "+f"((c)[3]) \
                 : "r"((a)[0]), "r"((a)[1]), "r"((a)[2]), "r"((a)[3]), \
                   "r"(b0), "r"(b1))

#define MMAH16816(c, a, b0, b1) \
    asm volatile("mma.sync.aligned.m16n8k16.row.col.f32.f16.f16.f32 " \
                 "{%0,%1,%2,%3}, {%4,%5,%6,%7}, {%8,%9}, {%0,%1,%2,%3};" \
                 : "+f"((c)[0]), "+f"((c)[1]), "+f"((c)[2]), "+f"((c)[3]) \
                 : "r"((a)[0]), "r"((a)[1]), "r"((a)[2]), "r"((a)[3]), \
                   "r"(b0), "r"(b1))

#define CP16(dst, src) \
    asm volatile("cp.async.cg.shared.global [%0], [%1], 16;" :: "r"(dst), "l"(src))
#define CP_COMMIT() asm volatile("cp.async.commit_group;" ::: "memory")
#define CP_WAIT0()  asm volatile("cp.async.wait_group 0;" ::: "memory")

__device__ __forceinline__ void decomp2_store(__nv_bfloat16* hp, __nv_bfloat16* lp,
                                              long long off, float x, float y) {
    __nv_bfloat16 hx = __float2bfloat16(x);
    __nv_bfloat16 hy = __float2bfloat16(y);
    *(__nv_bfloat162*)(hp + off) = __nv_bfloat162(hx, hy);
    *(__nv_bfloat162*)(lp + off) = __nv_bfloat162(__float2bfloat16(x - __bfloat162float(hx)),
                                                  __float2bfloat16(y - __bfloat162float(hy)));
}

__device__ __forceinline__ void decomp2h_store(__half* hp, __half* lp,
                                               long long off, float x, float y) {
    __half hx = __float2half(x);
    __half hy = __float2half(y);
    *(__half2*)(hp + off) = __halves2half2(hx, hy);
    *(__half2*)(lp + off) = __halves2half2(__float2half(x - __half2float(hx)),
                                           __float2half(y - __half2float(hy)));
}

// ===================== LayerNorm fused with bf16 decompose =====================
__global__ void ln_fused_kernel(const float* __restrict__ x,
                                const float* __restrict__ g,
                                const float* __restrict__ b,
                                float* __restrict__ out,          // may be null
                                __nv_bfloat16* __restrict__ oh,
                                __nv_bfloat16* __restrict__ ol,
                                int half_mode) {                  // 1: oh/ol are __half*
    __shared__ float xs[DD];
    __shared__ float red[256];
    const int row = blockIdx.x;
    const int tid = threadIdx.x;
    const float* xr = x + (long long)row * DD;

    float s = 0.f;
    for (int i = tid; i < DD; i += 256) { float t = xr[i]; xs[i] = t; s += t; }
    red[tid] = s; __syncthreads();
    for (int o = 128; o > 0; o >>= 1) { if (tid < o) red[tid] += red[tid + o]; __syncthreads(); }
    const float mean = red[0] * (1.f / DD);
    __syncthreads();

    float v = 0.f;
    for (int i = tid; i < DD; i += 256) { float d = xs[i] - mean; v += d * d; }
    red[tid] = v; __syncthreads();
    for (int o = 128; o > 0; o >>= 1) { if (tid < o) red[tid] += red[tid + o]; __syncthreads(); }
    const float rstd = rsqrtf(red[0] * (1.f / DD) + 1e-5f);

    const long long base = (long long)row * DD;
    for (int i = tid * 2; i < DD; i += 512) {
        float a0 = (xs[i] - mean) * rstd * g[i] + b[i];
        float a1 = (xs[i + 1] - mean) * rstd * g[i + 1] + b[i + 1];
        if (out) *(float2*)(out + base + i) = make_float2(a0, a1);
        if (half_mode) decomp2h_store((__half*)oh, (__half*)ol, base + i, a0, a1);
        else           decomp2_store(oh, ol, base + i, a0, a1);
    }
}

// ===================== softmax in place + decompose =====================
__global__ void softmax_kernel(float* __restrict__ w,
                               __nv_bfloat16* __restrict__ oh,
                               __nv_bfloat16* __restrict__ ol) {
    __shared__ float sc[SS_];
    __shared__ float red[256];
    const int qi = blockIdx.x, h = blockIdx.y, b = blockIdx.z;
    const int tid = threadIdx.x;
    const long long rbase = ((long long)(b * HH + h) * SS_ + qi) * SS_;
    float* wrow = w + rbase;
    const int n = qi + 1;

    float lmax = -1e30f;
    for (int j = tid; j < n; j += 256) { float t = wrow[j]; sc[j] = t; lmax = fmaxf(lmax, t); }
    red[tid] = lmax; __syncthreads();
    for (int o = 128; o > 0; o >>= 1) { if (tid < o) red[tid] = fmaxf(red[tid], red[tid + o]); __syncthreads(); }
    const float gmax = red[0];
    __syncthreads();

    float lsum = 0.f;
    for (int j = tid; j < n; j += 256) { float e = expf(sc[j] - gmax); sc[j] = e; lsum += e; }
    red[tid] = lsum; __syncthreads();
    for (int o = 128; o > 0; o >>= 1) { if (tid < o) red[tid] += red[tid + o]; __syncthreads(); }
    const float inv = 1.f / red[0];
    __syncthreads();

    for (int j = tid * 2; j < SS_; j += 512) {
        float x = (j < n) ? sc[j] * inv : 0.f;
        float y = (j + 1 < n) ? sc[j + 1] * inv : 0.f;
        *(float2*)(wrow + j) = make_float2(x, y);
        decomp2_store(oh, ol, rbase + j, x, y);
    }
}

// ===================== transpose+decompose weight [K,N] -> [N,K] (bf16 hi/lo) =====
__global__ void wtrans_kernel(const float* __restrict__ w,
                              __nv_bfloat16* __restrict__ bh,
                              __nv_bfloat16* __restrict__ bl,
                              int Kdim, int Ndim) {
    __shared__ float t[32][33];
    const int k0 = blockIdx.x * 32, n0 = blockIdx.y * 32;
    const int tx = threadIdx.x & 31, ty = threadIdx.x >> 5;
#pragma unroll
    for (int i = 0; i < 32; i += 8)
        t[ty + i][tx] = w[(long long)(k0 + ty + i) * Ndim + n0 + tx];
    __syncthreads();
#pragma unroll
    for (int i = 0; i < 32; i += 8) {
        float v = t[tx][ty + i];
        long long o = (long long)(n0 + ty + i) * Kdim + k0 + tx;
        __nv_bfloat16 h = __float2bfloat16(v);
        bh[o] = h;
        bl[o] = __float2bfloat16(v - __bfloat162float(h));
    }
}

// ===================== transpose weight [K,N] -> [N,K] (single fp16) ============
__global__ void wtrans_h_kernel(const float* __restrict__ w,
                                __half* __restrict__ bh,
                                int Kdim, int Ndim) {
    __shared__ float t[32][33];
    const int k0 = blockIdx.x * 32, n0 = blockIdx.y * 32;
    const int tx = threadIdx.x & 31, ty = threadIdx.x >> 5;
#pragma unroll
    for (int i = 0; i < 32; i += 8)
        t[ty + i][tx] = w[(long long)(k0 + ty + i) * Ndim + n0 + tx];
    __syncthreads();
#pragma unroll
    for (int i = 0; i < 32; i += 8)
        bh[(long long)(n0 + ty + i) * Kdim + k0 + tx] = __float2half(t[tx][ty + i]);
}

// ===================== transpose+decompose V [B,S,H,DH] -> [B,H,DH,S] ==========
__global__ void vtrans_kernel(const float* __restrict__ v,
                              __nv_bfloat16* __restrict__ bh,
                              __nv_bfloat16* __restrict__ bl) {
    __shared__ float t[32][33];
    const int bh_i = blockIdx.z;
    const int b = bh_i >> 4, h = bh_i & 15;
    const int s0 = blockIdx.x * 32, d0 = blockIdx.y * 32;
    const int tx = threadIdx.x & 31, ty = threadIdx.x >> 5;
#pragma unroll
    for (int i = 0; i < 32; i += 8)
        t[ty + i][tx] = v[(((long long)b * SS_ + s0 + ty + i) * HH + h) * DH_ + d0 + tx];
    __syncthreads();
#pragma unroll
    for (int i = 0; i < 32; i += 8) {
        float val = t[tx][ty + i];
        long long o = ((long long)bh_i * DH_ + d0 + ty + i) * SS_ + s0 + tx;
        __nv_bfloat16 hh2 = __float2bfloat16(val);
        bh[o] = hh2;
        bl[o] = __float2bfloat16(val - __bfloat162float(hh2));
    }
}

// ===================== pipelined mma.sync bf16x3 GEMM (best-known config) ======
// 128x128 CTA, BK=32, 2-stage, 2 CTA/SM, 8 warps of 64x32.
// act: 0 none, 1 gelu, 2 rope->Oh/Ol
// causal: 0 none, 1 skip blocks col0>row0+127, 2 limit K to row0+128
#define SA 40
#define TILEB (128 * SA * 2)
#define STAGEB (4 * TILEB)
#define GSMEM (2 * STAGEB)

__global__ __launch_bounds__(256, 2) void mma_gemm(
        const __nv_bfloat16* __restrict__ Ah, const __nv_bfloat16* __restrict__ Al,
        int lda, long long sAb, long long sAhS,
        const __nv_bfloat16* __restrict__ Bh, const __nv_bfloat16* __restrict__ Bl,
        int ldb, long long sBb, long long sBhS,
        float* __restrict__ C,
        __nv_bfloat16* __restrict__ Oh, __nv_bfloat16* __restrict__ Ol,
        int ldc, long long sCb, long long sCh,
        const float* __restrict__ bias,
        const float* __restrict__ res, int ldr, long long sRb, long long sRh,
        const int* __restrict__ pos,
        int K, int Hb, int act, int causal) {
    extern __shared__ char dsm[];

    const int row0 = blockIdx.y * 128;
    const int col0 = blockIdx.x * 128;
    if (causal == 1 && col0 > row0 + 127) return;

    const int tid = threadIdx.x;
    const int warp = tid >> 5, lane = tid & 31;
    const int wm = warp >> 2, wn = warp & 3;

    const int bz = blockIdx.z;
    const int b = bz / Hb, hh = bz % Hb;
    Ah += b * sAb + hh * sAhS;
    Al += b * sAb + hh * sAhS;
    Bh += b * sBb + hh * sBhS;
    Bl += b * sBb + hh * sBhS;
    const long long cOff = b * sCb + hh * sCh;
    if (C)  C += cOff;
    if (Oh) { Oh += cOff; Ol += cOff; }
    if (res) res += b * sRb + hh * sRh;

    const uint32_t u0 = smem_u32(dsm);

    float acc[4][4][4] = {};

    const int lr0 = tid >> 2, lc = (tid & 3) * 8;
    const int a_r = lane & 15, a_c = (lane >> 4) * 8;
    const int b_r = ((lane >> 4) << 3) + (lane & 7), b_c = ((lane >> 3) & 1) * 8;

    int nch = K / 32;
    if (causal == 2) { int lim = (row0 + 128) / 32; if (lim < nch) nch = lim; }

    auto load_chunk = [&](int ch, int st) {
        const int kb = ch * 32;
        const uint32_t base = u0 + st * STAGEB;
#pragma unroll
        for (int p = 0; p < 2; p++) {
            const int r = lr0 + p * 64;
            const long long ga = (long long)(row0 + r) * lda + kb + lc;
            const long long gb = (long long)(col0 + r) * ldb + kb + lc;
            const uint32_t so = (uint32_t)(r * SA + lc) * 2;
            CP16(base + so,             Ah + ga);
            CP16(base + TILEB + so,     Al + ga);
            CP16(base + 2 * TILEB + so, Bh + gb);
            CP16(base + 3 * TILEB + so, Bl + gb);
        }
    };

    load_chunk(0, 0);
    CP_COMMIT();

    for (int ch = 0; ch < nch; ch++) {
        CP_WAIT0();
        __syncthreads();
        if (ch + 1 < nch) { load_chunk(ch + 1, (ch + 1) & 1); CP_COMMIT(); }

        const uint32_t base = u0 + (ch & 1) * STAGEB;
        const uint32_t uAh = base, uAl = base + TILEB;
        const uint32_t uBh = base + 2 * TILEB, uBl = base + 3 * TILEB;

#pragma unroll
        for (int ks = 0; ks < 2; ks++) {
            const int kc = ks * 16;
            uint32_t af[4][4], fbh[2][4], fbl[2][4];
#pragma unroll
            for (int nb = 0; nb < 2; nb++) {
                const uint32_t off = (uint32_t)((wn * 32 + nb * 16 + b_r) * SA + kc + b_c) * 2;
                LDMX4(fbh[nb][0], fbh[nb][1], fbh[nb][2], fbh[nb][3], uBh + off);
                LDMX4(fbl[nb][0], fbl[nb][1], fbl[nb][2], fbl[nb][3], uBl + off);
            }
#pragma unroll
            for (int mi = 0; mi < 4; mi++) {
                const uint32_t off = (uint32_t)((wm * 64 + mi * 16 + a_r) * SA + kc + a_c) * 2;
                LDMX4(af[mi][0], af[mi][1], af[mi][2], af[mi][3], uAh + off);
            }
#pragma unroll
            for (int mi = 0; mi < 4; mi++)
#pragma unroll
                for (int ni = 0; ni < 4; ni++) {
                    MMA16816(acc[mi][ni], af[mi], fbh[ni >> 1][(ni & 1) * 2], fbh[ni >> 1][(ni & 1) * 2 + 1]);
                    MMA16816(acc[mi][ni], af[mi], fbl[ni >> 1][(ni & 1) * 2], fbl[ni >> 1][(ni & 1) * 2 + 1]);
                }
#pragma unroll
            for (int mi = 0; mi < 4; mi++) {
                const uint32_t off = (uint32_t)((wm * 64 + mi * 16 + a_r) * SA + kc + a_c) * 2;
                LDMX4(af[mi][0], af[mi][1], af[mi][2], af[mi][3], uAl + off);
            }
#pragma unroll
            for (int mi = 0; mi < 4; mi++)
#pragma unroll
                for (int ni = 0; ni < 4; ni++)
                    MMA16816(acc[mi][ni], af[mi], fbh[ni >> 1][(ni & 1) * 2], fbh[ni >> 1][(ni & 1) * 2 + 1]);
        }
        __syncthreads();
    }

    // epilogue
#pragma unroll
    for (int mi = 0; mi < 4; mi++) {
#pragma unroll
        for (int ni = 0; ni < 4; ni++) {
#pragma unroll
            for (int half = 0; half < 2; half++) {
                const long long r = row0 + wm * 64 + mi * 16 + (lane >> 2) + half * 8;
                const int cc = col0 + wn * 32 + ni * 8 + (lane & 3) * 2;
                float x = acc[mi][ni][half * 2];
                float y = acc[mi][ni][half * 2 + 1];
                if (bias) { x += bias[cc]; y += bias[cc + 1]; }
                if (act == 1) {
                    x = 0.5f * x * (1.f + erff(x * 0.70710678118654752f));
                    y = 0.5f * y * (1.f + erff(y * 0.70710678118654752f));
                } else if (act == 2) {
                    const int i = (cc & (DH_ - 1)) >> 1;
                    const float ang = (float)pos[r] * exp10f(-(float)i * (1.f / 16.f));
                    const float sn = sinf(ang), cs = cosf(ang);
                    const float nx = x * cs - y * sn;
                    y = y * cs + x * sn;
                    x = nx;
                }
                if (res) {
                    x += res[r * ldr + cc];
                    y += res[r * ldr + cc + 1];
                }
                if (C) *(float2*)(C + r * ldc + cc) = make_float2(x, y);
                if (Oh) decomp2_store(Oh, Ol, r * ldc + cc, x, y);
            }
        }
    }
}

// ===================== fp16 2-pass GEMM (FFN): A=hi/lo fp16, B=single fp16 ======
// Same 128x128 / BK32 / 2-stage / 2 CTA/SM / 8-warp 64x32 structure.
// act: 1 gelu -> fp16 hi/lo Oh/Ol ; 0 -> fp32 C (+bias, +res)
#define STAGEB_H (3 * TILEB)
#define GSMEM_H (2 * STAGEB_H)

__global__ __launch_bounds__(256, 2) void mma_gemm_h(
        const __half* __restrict__ Ah, const __half* __restrict__ Al, int lda,
        const __half* __restrict__ Bh, int ldb,
        float* __restrict__ C,
        __half* __restrict__ Oh, __half* __restrict__ Ol, int ldc,
        const float* __restrict__ bias,
        const float* __restrict__ res, int ldr,
        int K, int act) {
    extern __shared__ char dsm[];

    const int row0 = blockIdx.y * 128;
    const int col0 = blockIdx.x * 128;

    const int tid = threadIdx.x;
    const int warp = tid >> 5, lane = tid & 31;
    const int wm = warp >> 2, wn = warp & 3;

    const uint32_t u0 = smem_u32(dsm);

    float acc[4][4][4] = {};

    const int lr0 = tid >> 2, lc = (tid & 3) * 8;
    const int a_r = lane & 15, a_c = (lane >> 4) * 8;
    const int b_r = ((lane >> 4) << 3) + (lane & 7), b_c = ((lane >> 3) & 1) * 8;

    const int nch = K / 32;

    auto load_chunk = [&](int ch, int st) {
        const int kb = ch * 32;
        const uint32_t base = u0 + st * STAGEB_H;
#pragma unroll
        for (int p = 0; p < 2; p++) {
            const int r = lr0 + p * 64;
            const long long ga = (long long)(row0 + r) * lda + kb + lc;
            const long long gb = (long long)(col0 + r) * ldb + kb + lc;
            const uint32_t so = (uint32_t)(r * SA + lc) * 2;
            CP16(base + so,             Ah + ga);
            CP16(base + TILEB + so,     Al + ga);
            CP16(base + 2 * TILEB + so, Bh + gb);
        }
    };

    load_chunk(0, 0);
    CP_COMMIT();

    for (int ch = 0; ch < nch; ch++) {
        CP_WAIT0();
        __syncthreads();
        if (ch + 1 < nch) { load_chunk(ch + 1, (ch + 1) & 1); CP_COMMIT(); }

        const uint32_t base = u0 + (ch & 1) * STAGEB_H;
        const uint32_t uAh = base, uAl = base + TILEB;
        const uint32_t uBh = base + 2 * TILEB;

#pragma unroll
        for (int ks = 0; ks < 2; ks++) {
            const int kc = ks * 16;
            uint32_t af[4][4], fbh[2][4];
#pragma unroll
            for (int nb = 0; nb < 2; nb++) {
                const uint32_t off = (uint32_t)((wn * 32 + nb * 16 + b_r) * SA + kc + b_c) * 2;
                LDMX4(fbh[nb][0], fbh[nb][1], fbh[nb][2], fbh[nb][3], uBh + off);
            }
#pragma unroll
            for (int mi = 0; mi < 4; mi++) {
                const uint32_t off = (uint32_t)((wm * 64 + mi * 16 + a_r) * SA + kc + a_c) * 2;
                LDMX4(af[mi][0], af[mi][1], af[mi][2], af[mi][3], uAh + off);
            }
#pragma unroll
            for (int mi = 0; mi < 4; mi++)
#pragma unroll
                for (int ni = 0; ni < 4; ni++)
                    MMAH16816(acc[mi][ni], af[mi], fbh[ni >> 1][(ni & 1) * 2], fbh[ni >> 1][(ni & 1) * 2 + 1]);
#pragma unroll
            for (int mi = 0; mi < 4; mi++) {
                const uint32_t off = (uint32_t)((wm * 64 + mi * 16 + a_r) * SA + kc + a_c) * 2;
                LDMX4(af[mi][0], af[mi][1], af[mi][2], af[mi][3], uAl + off);
            }
#pragma unroll
            for (int mi = 0; mi < 4; mi++)
#pragma unroll
                for (int ni = 0; ni < 4; ni++)
                    MMAH16816(acc[mi][ni], af[mi], fbh[ni >> 1][(ni & 1) * 2], fbh[ni >> 1][(ni & 1) * 2 + 1]);
        }
        __syncthreads();
    }

    // epilogue
#pragma unroll
    for (int mi = 0; mi < 4; mi++) {
#pragma unroll
        for (int ni = 0; ni < 4; ni++) {
#pragma unroll
            for (int half = 0; half < 2; half++) {
                const long long r = row0 + wm * 64 + mi * 16 + (lane >> 2) + half * 8;
                const int cc = col0 + wn * 32 + ni * 8 + (lane & 3) * 2;
                float x = acc[mi][ni][half * 2];
                float y = acc[mi][ni][half * 2 + 1];
                if (bias) { x += bias[cc]; y += bias[cc + 1]; }
                if (act == 1) {
                    x = 0.5f * x * (1.f + erff(x * 0.70710678118654752f));
                    y = 0.5f * y * (1.f + erff(y * 0.70710678118654752f));
                }
                if (res) { x += res[r * ldr + cc]; y += res[r * ldr + cc + 1]; }
                if (C) *(float2*)(C + r * ldc + cc) = make_float2(x, y);
                if (Oh) decomp2h_store(Oh, Ol, r * ldc + cc, x, y);
            }
        }
    }
}

// ===================== host launch =====================
extern "C" void kernel_launch(void* const* d_in, const int* in_sizes, int n_in,
                              void* d_out, int out_size) {
    const float* hidden  = (const float*)d_in[0];
    const int*   pos     = (const int*)  d_in[1];
    const float* wq      = (const float*)d_in[2];
    const float* wk      = (const float*)d_in[3];
    const float* wv      = (const float*)d_in[4];
    const float* wo      = (const float*)d_in[5];
    const float* ln1_g   = (const float*)d_in[6];
    const float* ln1_b   = (const float*)d_in[7];
    const float* ln2_g   = (const float*)d_in[8];
    const float* ln2_b   = (const float*)d_in[9];
    const float* fc_in_w = (const float*)d_in[10];
    const float* fc_in_b = (const float*)d_in[11];
    const float* fc_out_w= (const float*)d_in[12];
    const float* fc_out_b= (const float*)d_in[13];

    float* out0 = (float*)d_out;                               // [B,S,D]
    float* out1 = out0 + (long long)BB * SS_ * DD;             // [B,H,S,S]

    float *h, *v, *res;
    __nv_bfloat16 *Ah, *Al, *Bh, *Bl, *Ch, *Cl, *Kh, *Kl;
    cudaGetSymbolAddress((void**)&h,   g_h);
    cudaGetSymbolAddress((void**)&v,   g_v);
    cudaGetSymbolAddress((void**)&res, g_res);
    cudaGetSymbolAddress((void**)&Ah,  g_Ah);
    cudaGetSymbolAddress((void**)&Al,  g_Al);
    cudaGetSymbolAddress((void**)&Bh,  g_Bh);
    cudaGetSymbolAddress((void**)&Bl,  g_Bl);
    cudaGetSymbolAddress((void**)&Ch,  g_Ch);
    cudaGetSymbolAddress((void**)&Cl,  g_Cl);
    cudaGetSymbolAddress((void**)&Kh,  g_Kh);
    cudaGetSymbolAddress((void**)&Kl,  g_Kl);

    cudaFuncSetAttribute(mma_gemm,   cudaFuncAttributeMaxDynamicSharedMemorySize, GSMEM);
    cudaFuncSetAttribute(mma_gemm_h, cudaFuncAttributeMaxDynamicSharedMemorySize, GSMEM_H);

    // 1. LN1 -> bf16 hi/lo only
    ln_fused_kernel<<<ROWS, 256>>>(hidden, ln1_g, ln1_b, nullptr, Ah, Al, 0);

    // 2. QKV. q,k fuse RoPE in epilogue and emit hi/lo directly; v stays fp32.
    dim3 gQ(DD / 128, ROWS / 128, 1);
    dim3 gW(DD / 32, DD / 32);
    wtrans_kernel<<<gW, 256>>>(wq, Bh, Bl, DD, DD);
    mma_gemm<<<gQ, 256, GSMEM>>>(Ah, Al, DD, 0, 0, Bh, Bl, DD, 0, 0,
                                 nullptr, Ch, Cl, DD, 0, 0,
                                 nullptr, nullptr, 0, 0, 0, pos, DD, 1, 2, 0);
    wtrans_kernel<<<gW, 256>>>(wk, Bh, Bl, DD, DD);
    mma_gemm<<<gQ, 256, GSMEM>>>(Ah, Al, DD, 0, 0, Bh, Bl, DD, 0, 0,
                                 nullptr, Kh, Kl, DD, 0, 0,
                                 nullptr, nullptr, 0, 0, 0, pos, DD, 1, 2, 0);
    wtrans_kernel<<<gW, 256>>>(wv, Bh, Bl, DD, DD);
    mma_gemm<<<gQ, 256, GSMEM>>>(Ah, Al, DD, 0, 0, Bh, Bl, DD, 0, 0,
                                 v, nullptr, nullptr, DD, 0, 0,
                                 nullptr, nullptr, 0, 0, 0, nullptr, DD, 1, 0, 0);

    // 3. scores = q @ k^T (causal blocks) -> out1 fp32
    {
        dim3 gS(SS_ / 128, SS_ / 128, BB * HH);
        mma_gemm<<<gS, 256, GSMEM>>>(
            Ch, Cl, DD, (long long)SS_ * DD, DH_,
            Kh, Kl, DD, (long long)SS_ * DD, DH_,
            out1, nullptr, nullptr, SS_, (long long)HH * SS_ * SS_, (long long)SS_ * SS_,
            nullptr, nullptr, 0, 0, 0, nullptr, DH_, HH, 0, 1);
    }

    // 4. softmax in place + decompose -> Ah/Al
    {
        dim3 gA(SS_, HH, BB);
        softmax_kernel<<<gA, 256>>>(out1, Ah, Al);
    }

    // 5. v^T decompose -> Bh/Bl; ctx = weights @ v (bf16 hi/lo -> Ch/Cl)
    {
        dim3 gVT(SS_ / 32, DH_ / 32, BB * HH);
        vtrans_kernel<<<gVT, 256>>>(v, Bh, Bl);
        dim3 gV(DH_ / 128, SS_ / 128, BB * HH);
        mma_gemm<<<gV, 256, GSMEM>>>(
            Ah, Al, SS_, (long long)HH * SS_ * SS_, (long long)SS_ * SS_,
            Bh, Bl, SS_, (long long)HH * DH_ * SS_, (long long)DH_ * SS_,
            nullptr, Ch, Cl, DD, (long long)SS_ * DD, DH_,
            nullptr, nullptr, 0, 0, 0, nullptr, SS_, HH, 0, 2);
    }

    // 6. res = ctx @ wo + hidden (fp32)
    wtrans_kernel<<<gW, 256>>>(wo, Bh, Bl, DD, DD);
    mma_gemm<<<gQ, 256, GSMEM>>>(Ch, Cl, DD, 0, 0, Bh, Bl, DD, 0, 0,
                                 res, nullptr, nullptr, DD, 0, 0,
                                 nullptr, hidden, DD, 0, 0, nullptr, DD, 1, 0, 0);

    // 7. LN2 -> h fp32 + fp16 hi/lo (Ah/Al reinterpret)
    ln_fused_kernel<<<ROWS, 256>>>(res, ln2_g, ln2_b, h, Ah, Al, 1);

    // 8. ffn = gelu(h2 @ fc_in + b) -> fp16 hi/lo Ch/Cl  [fp16 2-pass]
    {
        dim3 gW1(DD / 32, FF_ / 32);
        wtrans_h_kernel<<<gW1, 256>>>(fc_in_w, (__half*)Bh, DD, FF_);
        dim3 gF1(FF_ / 128, ROWS / 128, 1);
        mma_gemm_h<<<gF1, 256, GSMEM_H>>>((__half*)Ah, (__half*)Al, DD,
                                          (__half*)Bh, DD,
                                          nullptr, (__half*)Ch, (__half*)Cl, FF_,
                                          fc_in_b, nullptr, 0, DD, 1);
    }

    // 9. out0 = ffn @ fc_out + b + h2  [fp16 2-pass]
    {
        dim3 gW2(FF_ / 32, DD / 32);
        wtrans_h_kernel<<<gW2, 256>>>(fc_out_w, (__half*)Bh, FF_, DD);
        dim3 gF2(DD / 128, ROWS / 128, 1);
        mma_gemm_h<<<gF2, 256, GSMEM_H>>>((__half*)Ch, (__half*)Cl, FF_,
                                          (__half*)Bh, FF_,
                                          out0, nullptr, nullptr, DD,
                                          fc_out_b, h, DD, FF_, 0);
    }
}

// round 12
// speedup vs baseline: 1.3446x; 1.0334x over previous
#include <cuda_runtime.h>
#include <cuda_bf16.h>
#include <cuda_fp16.h>
#include <math.h>
#include <stdint.h>

// Problem dims (fixed)
#define BB 2
#define SS_ 2048
#define DD 2048
#define HH 16
#define DH_ 128
#define FF_ 8192
#define ROWS 4096            // B*S

// ---------------- scratch ----------------
__device__ float g_h   [(size_t)ROWS * DD];   // h2 (LN2 out, fp32)
__device__ float g_v   [(size_t)ROWS * DD];
__device__ float g_res [(size_t)ROWS * DD];

#define AMAX ((size_t)BB * HH * SS_ * SS_)
#define BMAX ((size_t)DD * FF_)
#define CMAX ((size_t)ROWS * FF_)
__device__ __nv_bfloat16 g_Ah[AMAX];
__device__ __nv_bfloat16 g_Al[AMAX];
__device__ __nv_bfloat16 g_Bh[BMAX];
__device__ __nv_bfloat16 g_Bl[BMAX];
__device__ __nv_bfloat16 g_Ch[CMAX];
__device__ __nv_bfloat16 g_Cl[CMAX];
__device__ __nv_bfloat16 g_Kh[(size_t)ROWS * DD];
__device__ __nv_bfloat16 g_Kl[(size_t)ROWS * DD];

__device__ __forceinline__ uint32_t smem_u32(const void* p) {
    uint32_t a;
    asm("{ .reg .u64 t; cvta.to.shared.u64 t, %1; cvt.u32.u64 %0, t; }" : "=r"(a) : "l"(p));
    return a;
}

#define LDMX4(r0, r1, r2, r3, addr) \
    asm volatile("ldmatrix.sync.aligned.m8n8.x4.shared.b16 {%0,%1,%2,%3}, [%4];" \
                 : "=r"(r0), "=r"(r1), "=r"(r2), "=r"(r3) : "r"(addr))

#define MMA16816(c, a, b0, b1) \
    asm volatile("mma.sync.aligned.m16n8k16.row.col.f32.bf16.bf16.f32 " \
                 "{%0,%1,%2,%3}, {%4,%5,%6,%7}, {%8,%9}, {%0,%1,%2,%3};" \
                 : "+f"((c)[0]), "+f"((c)[1]), "+f"((c)[2]), "+f"((c)[3]) \
                 : "r"((a)[0]), "r"((a)[1]), "r"((a)[2]), "r"((a)[3]), \
                   "r"(b0), "r"(b1))

#define MMAH16816(c, a, b0, b1) \
    asm volatile("mma.sync.aligned.m16n8k16.row.col.f32.f16.f16.f32 " \
                 "{%0,%1,%2,%3}, {%4,%5,%6,%7}, {%8,%9}, {%0,%1,%2,%3};" \
                 : "+f"((c)[0]), "+f"((c)[1]), "+f"((c)[2]), "+f"((c)[3]) \
                 : "r"((a)[0]), "r"((a)[1]), "r"((a)[2]), "r"((a)[3]), \
                   "r"(b0), "r"(b1))

#define CP16(dst, src) \
    asm volatile("cp.async.cg.shared.global [%0], [%1], 16;" :: "r"(dst), "l"(src))
#define CP_COMMIT() asm volatile("cp.async.commit_group;" ::: "memory")
#define CP_WAIT0()  asm volatile("cp.async.wait_group 0;" ::: "memory")

__device__ __forceinline__ void decomp2_store(__nv_bfloat16* hp, __nv_bfloat16* lp,
                                              long long off, float x, float y) {
    __nv_bfloat16 hx = __float2bfloat16(x);
    __nv_bfloat16 hy = __float2bfloat16(y);
    *(__nv_bfloat162*)(hp + off) = __nv_bfloat162(hx, hy);
    *(__nv_bfloat162*)(lp + off) = __nv_bfloat162(__float2bfloat16(x - __bfloat162float(hx)),
                                                  __float2bfloat16(y - __bfloat162float(hy)));
}

__device__ __forceinline__ void decomp2h_store(__half* hp, __half* lp,
                                               long long off, float x, float y) {
    __half hx = __float2half(x);
    __half hy = __float2half(y);
    *(__half2*)(hp + off) = __halves2half2(hx, hy);
    *(__half2*)(lp + off) = __halves2half2(__float2half(x - __half2float(hx)),
                                           __float2half(y - __half2float(hy)));
}

// ===================== LayerNorm fused with decompose =====================
__global__ void ln_fused_kernel(const float* __restrict__ x,
                                const float* __restrict__ g,
                                const float* __restrict__ b,
                                float* __restrict__ out,          // may be null
                                __nv_bfloat16* __restrict__ oh,
                                __nv_bfloat16* __restrict__ ol,
                                int half_mode) {                  // 1: oh/ol are __half*
    __shared__ float xs[DD];
    __shared__ float red[256];
    const int row = blockIdx.x;
    const int tid = threadIdx.x;
    const float* xr = x + (long long)row * DD;

    float s = 0.f;
    for (int i = tid; i < DD; i += 256) { float t = xr[i]; xs[i] = t; s += t; }
    red[tid] = s; __syncthreads();
    for (int o = 128; o > 0; o >>= 1) { if (tid < o) red[tid] += red[tid + o]; __syncthreads(); }
    const float mean = red[0] * (1.f / DD);
    __syncthreads();

    float v = 0.f;
    for (int i = tid; i < DD; i += 256) { float d = xs[i] - mean; v += d * d; }
    red[tid] = v; __syncthreads();
    for (int o = 128; o > 0; o >>= 1) { if (tid < o) red[tid] += red[tid + o]; __syncthreads(); }
    const float rstd = rsqrtf(red[0] * (1.f / DD) + 1e-5f);

    const long long base = (long long)row * DD;
    for (int i = tid * 2; i < DD; i += 512) {
        float a0 = (xs[i] - mean) * rstd * g[i] + b[i];
        float a1 = (xs[i + 1] - mean) * rstd * g[i + 1] + b[i + 1];
        if (out) *(float2*)(out + base + i) = make_float2(a0, a1);
        if (half_mode) decomp2h_store((__half*)oh, (__half*)ol, base + i, a0, a1);
        else           decomp2_store(oh, ol, base + i, a0, a1);
    }
}

// ===================== softmax in place + fp16 hi/lo decompose ==================
__global__ void softmax_kernel(float* __restrict__ w,
                               __half* __restrict__ oh,
                               __half* __restrict__ ol) {
    __shared__ float sc[SS_];
    __shared__ float red[256];
    const int qi = blockIdx.x, h = blockIdx.y, b = blockIdx.z;
    const int tid = threadIdx.x;
    const long long rbase = ((long long)(b * HH + h) * SS_ + qi) * SS_;
    float* wrow = w + rbase;
    const int n = qi + 1;

    float lmax = -1e30f;
    for (int j = tid; j < n; j += 256) { float t = wrow[j]; sc[j] = t; lmax = fmaxf(lmax, t); }
    red[tid] = lmax; __syncthreads();
    for (int o = 128; o > 0; o >>= 1) { if (tid < o) red[tid] = fmaxf(red[tid], red[tid + o]); __syncthreads(); }
    const float gmax = red[0];
    __syncthreads();

    float lsum = 0.f;
    for (int j = tid; j < n; j += 256) { float e = expf(sc[j] - gmax); sc[j] = e; lsum += e; }
    red[tid] = lsum; __syncthreads();
    for (int o = 128; o > 0; o >>= 1) { if (tid < o) red[tid] += red[tid + o]; __syncthreads(); }
    const float inv = 1.f / red[0];
    __syncthreads();

    for (int j = tid * 2; j < SS_; j += 512) {
        float x = (j < n) ? sc[j] * inv : 0.f;
        float y = (j + 1 < n) ? sc[j + 1] * inv : 0.f;
        *(float2*)(wrow + j) = make_float2(x, y);
        decomp2h_store(oh, ol, rbase + j, x, y);
    }
}

// ===================== transpose+decompose weight [K,N] -> [N,K] (bf16 hi/lo) =====
__global__ void wtrans_kernel(const float* __restrict__ w,
                              __nv_bfloat16* __restrict__ bh,
                              __nv_bfloat16* __restrict__ bl,
                              int Kdim, int Ndim) {
    __shared__ float t[32][33];
    const int k0 = blockIdx.x * 32, n0 = blockIdx.y * 32;
    const int tx = threadIdx.x & 31, ty = threadIdx.x >> 5;
#pragma unroll
    for (int i = 0; i < 32; i += 8)
        t[ty + i][tx] = w[(long long)(k0 + ty + i) * Ndim + n0 + tx];
    __syncthreads();
#pragma unroll
    for (int i = 0; i < 32; i += 8) {
        float v = t[tx][ty + i];
        long long o = (long long)(n0 + ty + i) * Kdim + k0 + tx;
        __nv_bfloat16 h = __float2bfloat16(v);
        bh[o] = h;
        bl[o] = __float2bfloat16(v - __bfloat162float(h));
    }
}

// ===================== transpose weight [K,N] -> [N,K] (single fp16) ============
__global__ void wtrans_h_kernel(const float* __restrict__ w,
                                __half* __restrict__ bh,
                                int Kdim, int Ndim) {
    __shared__ float t[32][33];
    const int k0 = blockIdx.x * 32, n0 = blockIdx.y * 32;
    const int tx = threadIdx.x & 31, ty = threadIdx.x >> 5;
#pragma unroll
    for (int i = 0; i < 32; i += 8)
        t[ty + i][tx] = w[(long long)(k0 + ty + i) * Ndim + n0 + tx];
    __syncthreads();
#pragma unroll
    for (int i = 0; i < 32; i += 8)
        bh[(long long)(n0 + ty + i) * Kdim + k0 + tx] = __float2half(t[tx][ty + i]);
}

// ===================== transpose V [B,S,H,DH] -> [B,H,DH,S] single fp16 ==========
__global__ void vtrans_kernel(const float* __restrict__ v,
                              __half* __restrict__ bh) {
    __shared__ float t[32][33];
    const int bh_i = blockIdx.z;
    const int b = bh_i >> 4, h = bh_i & 15;
    const int s0 = blockIdx.x * 32, d0 = blockIdx.y * 32;
    const int tx = threadIdx.x & 31, ty = threadIdx.x >> 5;
#pragma unroll
    for (int i = 0; i < 32; i += 8)
        t[ty + i][tx] = v[(((long long)b * SS_ + s0 + ty + i) * HH + h) * DH_ + d0 + tx];
    __syncthreads();
#pragma unroll
    for (int i = 0; i < 32; i += 8) {
        long long o = ((long long)bh_i * DH_ + d0 + ty + i) * SS_ + s0 + tx;
        bh[o] = __float2half(t[tx][ty + i]);
    }
}

// ===================== pipelined mma.sync bf16x3 GEMM (q/k path) ===============
// 128x128 CTA, BK=32, 2-stage, 2 CTA/SM, 8 warps of 64x32.
// act: 0 none, 1 gelu, 2 rope->Oh/Ol
// causal: 0 none, 1 skip blocks col0>row0+127, 2 limit K to row0+128
#define SA 40
#define TILEB (128 * SA * 2)
#define STAGEB (4 * TILEB)
#define GSMEM (2 * STAGEB)

__global__ __launch_bounds__(256, 2) void mma_gemm(
        const __nv_bfloat16* __restrict__ Ah, const __nv_bfloat16* __restrict__ Al,
        int lda, long long sAb, long long sAhS,
        const __nv_bfloat16* __restrict__ Bh, const __nv_bfloat16* __restrict__ Bl,
        int ldb, long long sBb, long long sBhS,
        float* __restrict__ C,
        __nv_bfloat16* __restrict__ Oh, __nv_bfloat16* __restrict__ Ol,
        int ldc, long long sCb, long long sCh,
        const float* __restrict__ bias,
        const float* __restrict__ res, int ldr, long long sRb, long long sRh,
        const int* __restrict__ pos,
        int K, int Hb, int act, int causal) {
    extern __shared__ char dsm[];

    const int row0 = blockIdx.y * 128;
    const int col0 = blockIdx.x * 128;
    if (causal == 1 && col0 > row0 + 127) return;

    const int tid = threadIdx.x;
    const int warp = tid >> 5, lane = tid & 31;
    const int wm = warp >> 2, wn = warp & 3;

    const int bz = blockIdx.z;
    const int b = bz / Hb, hh = bz % Hb;
    Ah += b * sAb + hh * sAhS;
    Al += b * sAb + hh * sAhS;
    Bh += b * sBb + hh * sBhS;
    Bl += b * sBb + hh * sBhS;
    const long long cOff = b * sCb + hh * sCh;
    if (C)  C += cOff;
    if (Oh) { Oh += cOff; Ol += cOff; }
    if (res) res += b * sRb + hh * sRh;

    const uint32_t u0 = smem_u32(dsm);

    float acc[4][4][4] = {};

    const int lr0 = tid >> 2, lc = (tid & 3) * 8;
    const int a_r = lane & 15, a_c = (lane >> 4) * 8;
    const int b_r = ((lane >> 4) << 3) + (lane & 7), b_c = ((lane >> 3) & 1) * 8;

    int nch = K / 32;
    if (causal == 2) { int lim = (row0 + 128) / 32; if (lim < nch) nch = lim; }

    auto load_chunk = [&](int ch, int st) {
        const int kb = ch * 32;
        const uint32_t base = u0 + st * STAGEB;
#pragma unroll
        for (int p = 0; p < 2; p++) {
            const int r = lr0 + p * 64;
            const long long ga = (long long)(row0 + r) * lda + kb + lc;
            const long long gb = (long long)(col0 + r) * ldb + kb + lc;
            const uint32_t so = (uint32_t)(r * SA + lc) * 2;
            CP16(base + so,             Ah + ga);
            CP16(base + TILEB + so,     Al + ga);
            CP16(base + 2 * TILEB + so, Bh + gb);
            CP16(base + 3 * TILEB + so, Bl + gb);
        }
    };

    load_chunk(0, 0);
    CP_COMMIT();

    for (int ch = 0; ch < nch; ch++) {
        CP_WAIT0();
        __syncthreads();
        if (ch + 1 < nch) { load_chunk(ch + 1, (ch + 1) & 1); CP_COMMIT(); }

        const uint32_t base = u0 + (ch & 1) * STAGEB;
        const uint32_t uAh = base, uAl = base + TILEB;
        const uint32_t uBh = base + 2 * TILEB, uBl = base + 3 * TILEB;

#pragma unroll
        for (int ks = 0; ks < 2; ks++) {
            const int kc = ks * 16;
            uint32_t af[4][4], fbh[2][4], fbl[2][4];
#pragma unroll
            for (int nb = 0; nb < 2; nb++) {
                const uint32_t off = (uint32_t)((wn * 32 + nb * 16 + b_r) * SA + kc + b_c) * 2;
                LDMX4(fbh[nb][0], fbh[nb][1], fbh[nb][2], fbh[nb][3], uBh + off);
                LDMX4(fbl[nb][0], fbl[nb][1], fbl[nb][2], fbl[nb][3], uBl + off);
            }
#pragma unroll
            for (int mi = 0; mi < 4; mi++) {
                const uint32_t off = (uint32_t)((wm * 64 + mi * 16 + a_r) * SA + kc + a_c) * 2;
                LDMX4(af[mi][0], af[mi][1], af[mi][2], af[mi][3], uAh + off);
            }
#pragma unroll
            for (int mi = 0; mi < 4; mi++)
#pragma unroll
                for (int ni = 0; ni < 4; ni++) {
                    MMA16816(acc[mi][ni], af[mi], fbh[ni >> 1][(ni & 1) * 2], fbh[ni >> 1][(ni & 1) * 2 + 1]);
                    MMA16816(acc[mi][ni], af[mi], fbl[ni >> 1][(ni & 1) * 2], fbl[ni >> 1][(ni & 1) * 2 + 1]);
                }
#pragma unroll
            for (int mi = 0; mi < 4; mi++) {
                const uint32_t off = (uint32_t)((wm * 64 + mi * 16 + a_r) * SA + kc + a_c) * 2;
                LDMX4(af[mi][0], af[mi][1], af[mi][2], af[mi][3], uAl + off);
            }
#pragma unroll
            for (int mi = 0; mi < 4; mi++)
#pragma unroll
                for (int ni = 0; ni < 4; ni++)
                    MMA16816(acc[mi][ni], af[mi], fbh[ni >> 1][(ni & 1) * 2], fbh[ni >> 1][(ni & 1) * 2 + 1]);
        }
        __syncthreads();
    }

    // epilogue
#pragma unroll
    for (int mi = 0; mi < 4; mi++) {
#pragma unroll
        for (int ni = 0; ni < 4; ni++) {
#pragma unroll
            for (int half = 0; half < 2; half++) {
                const long long r = row0 + wm * 64 + mi * 16 + (lane >> 2) + half * 8;
                const int cc = col0 + wn * 32 + ni * 8 + (lane & 3) * 2;
                float x = acc[mi][ni][half * 2];
                float y = acc[mi][ni][half * 2 + 1];
                if (bias) { x += bias[cc]; y += bias[cc + 1]; }
                if (act == 1) {
                    x = 0.5f * x * (1.f + erff(x * 0.70710678118654752f));
                    y = 0.5f * y * (1.f + erff(y * 0.70710678118654752f));
                } else if (act == 2) {
                    const int i = (cc & (DH_ - 1)) >> 1;
                    const float ang = (float)pos[r] * exp10f(-(float)i * (1.f / 16.f));
                    const float sn = sinf(ang), cs = cosf(ang);
                    const float nx = x * cs - y * sn;
                    y = y * cs + x * sn;
                    x = nx;
                }
                if (res) {
                    x += res[r * ldr + cc];
                    y += res[r * ldr + cc + 1];
                }
                if (C) *(float2*)(C + r * ldc + cc) = make_float2(x, y);
                if (Oh) decomp2_store(Oh, Ol, r * ldc + cc, x, y);
            }
        }
    }
}

// ===================== fp16 2-pass GEMM: A=hi/lo fp16, B=single fp16 ============
// Same 128x128 / BK32 / 2-stage / 2 CTA/SM / 8-warp 64x32 structure.
// Batched (Hb heads) + causal=2 K-limit supported.
// act: 1 gelu -> fp16 Oh/Ol ; 0 -> outputs as flagged
#define STAGEB_H (3 * TILEB)
#define GSMEM_H (2 * STAGEB_H)

__global__ __launch_bounds__(256, 2) void mma_gemm_h(
        const __half* __restrict__ Ah, const __half* __restrict__ Al,
        int lda, long long sAb, long long sAhS,
        const __half* __restrict__ Bh,
        int ldb, long long sBb, long long sBhS,
        float* __restrict__ C,
        __half* __restrict__ Oh, __half* __restrict__ Ol,
        int ldc, long long sCb, long long sCh,
        const float* __restrict__ bias,
        const float* __restrict__ res, int ldr,
        int K, int Hb, int act, int causal) {
    extern __shared__ char dsm[];

    const int row0 = blockIdx.y * 128;
    const int col0 = blockIdx.x * 128;

    const int tid = threadIdx.x;
    const int warp = tid >> 5, lane = tid & 31;
    const int wm = warp >> 2, wn = warp & 3;

    const int bz = blockIdx.z;
    const int b = bz / Hb, hh = bz % Hb;
    Ah += b * sAb + hh * sAhS;
    Al += b * sAb + hh * sAhS;
    Bh += b * sBb + hh * sBhS;
    const long long cOff = b * sCb + hh * sCh;
    if (C)  C += cOff;
    if (Oh) { Oh += cOff; Ol += cOff; }

    const uint32_t u0 = smem_u32(dsm);

    float acc[4][4][4] = {};

    const int lr0 = tid >> 2, lc = (tid & 3) * 8;
    const int a_r = lane & 15, a_c = (lane >> 4) * 8;
    const int b_r = ((lane >> 4) << 3) + (lane & 7), b_c = ((lane >> 3) & 1) * 8;

    int nch = K / 32;
    if (causal == 2) { int lim = (row0 + 128) / 32; if (lim < nch) nch = lim; }

    auto load_chunk = [&](int ch, int st) {
        const int kb = ch * 32;
        const uint32_t base = u0 + st * STAGEB_H;
#pragma unroll
        for (int p = 0; p < 2; p++) {
            const int r = lr0 + p * 64;
            const long long ga = (long long)(row0 + r) * lda + kb + lc;
            const long long gb = (long long)(col0 + r) * ldb + kb + lc;
            const uint32_t so = (uint32_t)(r * SA + lc) * 2;
            CP16(base + so,             Ah + ga);
            CP16(base + TILEB + so,     Al + ga);
            CP16(base + 2 * TILEB + so, Bh + gb);
        }
    };

    load_chunk(0, 0);
    CP_COMMIT();

    for (int ch = 0; ch < nch; ch++) {
        CP_WAIT0();
        __syncthreads();
        if (ch + 1 < nch) { load_chunk(ch + 1, (ch + 1) & 1); CP_COMMIT(); }

        const uint32_t base = u0 + (ch & 1) * STAGEB_H;
        const uint32_t uAh = base, uAl = base + TILEB;
        const uint32_t uBh = base + 2 * TILEB;

#pragma unroll
        for (int ks = 0; ks < 2; ks++) {
            const int kc = ks * 16;
            uint32_t af[4][4], fbh[2][4];
#pragma unroll
            for (int nb = 0; nb < 2; nb++) {
                const uint32_t off = (uint32_t)((wn * 32 + nb * 16 + b_r) * SA + kc + b_c) * 2;
                LDMX4(fbh[nb][0], fbh[nb][1], fbh[nb][2], fbh[nb][3], uBh + off);
            }
#pragma unroll
            for (int mi = 0; mi < 4; mi++) {
                const uint32_t off = (uint32_t)((wm * 64 + mi * 16 + a_r) * SA + kc + a_c) * 2;
                LDMX4(af[mi][0], af[mi][1], af[mi][2], af[mi][3], uAh + off);
            }
#pragma unroll
            for (int mi = 0; mi < 4; mi++)
#pragma unroll
                for (int ni = 0; ni < 4; ni++)
                    MMAH16816(acc[mi][ni], af[mi], fbh[ni >> 1][(ni & 1) * 2], fbh[ni >> 1][(ni & 1) * 2 + 1]);
#pragma unroll
            for (int mi = 0; mi < 4; mi++) {
                const uint32_t off = (uint32_t)((wm * 64 + mi * 16 + a_r) * SA + kc + a_c) * 2;
                LDMX4(af[mi][0], af[mi][1], af[mi][2], af[mi][3], uAl + off);
            }
#pragma unroll
            for (int mi = 0; mi < 4; mi++)
#pragma unroll
                for (int ni = 0; ni < 4; ni++)
                    MMAH16816(acc[mi][ni], af[mi], fbh[ni >> 1][(ni & 1) * 2], fbh[ni >> 1][(ni & 1) * 2 + 1]);
        }
        __syncthreads();
    }

    // epilogue
#pragma unroll
    for (int mi = 0; mi < 4; mi++) {
#pragma unroll
        for (int ni = 0; ni < 4; ni++) {
#pragma unroll
            for (int half = 0; half < 2; half++) {
                const long long r = row0 + wm * 64 + mi * 16 + (lane >> 2) + half * 8;
                const int cc = col0 + wn * 32 + ni * 8 + (lane & 3) * 2;
                float x = acc[mi][ni][half * 2];
                float y = acc[mi][ni][half * 2 + 1];
                if (bias) { x += bias[cc]; y += bias[cc + 1]; }
                if (act == 1) {
                    x = 0.5f * x * (1.f + erff(x * 0.70710678118654752f));
                    y = 0.5f * y * (1.f + erff(y * 0.70710678118654752f));
                }
                if (res) { x += res[r * ldr + cc]; y += res[r * ldr + cc + 1]; }
                if (C) *(float2*)(C + r * ldc + cc) = make_float2(x, y);
                if (Oh) decomp2h_store(Oh, Ol, r * ldc + cc, x, y);
            }
        }
    }
}

// ===================== host launch =====================
extern "C" void kernel_launch(void* const* d_in, const int* in_sizes, int n_in,
                              void* d_out, int out_size) {
    const float* hidden  = (const float*)d_in[0];
    const int*   pos     = (const int*)  d_in[1];
    const float* wq      = (const float*)d_in[2];
    const float* wk      = (const float*)d_in[3];
    const float* wv      = (const float*)d_in[4];
    const float* wo      = (const float*)d_in[5];
    const float* ln1_g   = (const float*)d_in[6];
    const float* ln1_b   = (const float*)d_in[7];
    const float* ln2_g   = (const float*)d_in[8];
    const float* ln2_b   = (const float*)d_in[9];
    const float* fc_in_w = (const float*)d_in[10];
    const float* fc_in_b = (const float*)d_in[11];
    const float* fc_out_w= (const float*)d_in[12];
    const float* fc_out_b= (const float*)d_in[13];

    float* out0 = (float*)d_out;                               // [B,S,D]
    float* out1 = out0 + (long long)BB * SS_ * DD;             // [B,H,S,S]

    float *h, *v, *res;
    __nv_bfloat16 *Ah, *Al, *Bh, *Bl, *Ch, *Cl, *Kh, *Kl;
    cudaGetSymbolAddress((void**)&h,   g_h);
    cudaGetSymbolAddress((void**)&v,   g_v);
    cudaGetSymbolAddress((void**)&res, g_res);
    cudaGetSymbolAddress((void**)&Ah,  g_Ah);
    cudaGetSymbolAddress((void**)&Al,  g_Al);
    cudaGetSymbolAddress((void**)&Bh,  g_Bh);
    cudaGetSymbolAddress((void**)&Bl,  g_Bl);
    cudaGetSymbolAddress((void**)&Ch,  g_Ch);
    cudaGetSymbolAddress((void**)&Cl,  g_Cl);
    cudaGetSymbolAddress((void**)&Kh,  g_Kh);
    cudaGetSymbolAddress((void**)&Kl,  g_Kl);

    cudaFuncSetAttribute(mma_gemm,   cudaFuncAttributeMaxDynamicSharedMemorySize, GSMEM);
    cudaFuncSetAttribute(mma_gemm_h, cudaFuncAttributeMaxDynamicSharedMemorySize, GSMEM_H);

    // 1. LN1 -> bf16 hi/lo only
    ln_fused_kernel<<<ROWS, 256>>>(hidden, ln1_g, ln1_b, nullptr, Ah, Al, 0);

    // 2. QKV. q,k fuse RoPE in epilogue and emit bf16 hi/lo; v stays fp32. (bf16x3)
    dim3 gQ(DD / 128, ROWS / 128, 1);
    dim3 gW(DD / 32, DD / 32);
    wtrans_kernel<<<gW, 256>>>(wq, Bh, Bl, DD, DD);
    mma_gemm<<<gQ, 256, GSMEM>>>(Ah, Al, DD, 0, 0, Bh, Bl, DD, 0, 0,
                                 nullptr, Ch, Cl, DD, 0, 0,
                                 nullptr, nullptr, 0, 0, 0, pos, DD, 1, 2, 0);
    wtrans_kernel<<<gW, 256>>>(wk, Bh, Bl, DD, DD);
    mma_gemm<<<gQ, 256, GSMEM>>>(Ah, Al, DD, 0, 0, Bh, Bl, DD, 0, 0,
                                 nullptr, Kh, Kl, DD, 0, 0,
                                 nullptr, nullptr, 0, 0, 0, pos, DD, 1, 2, 0);
    wtrans_kernel<<<gW, 256>>>(wv, Bh, Bl, DD, DD);
    mma_gemm<<<gQ, 256, GSMEM>>>(Ah, Al, DD, 0, 0, Bh, Bl, DD, 0, 0,
                                 v, nullptr, nullptr, DD, 0, 0,
                                 nullptr, nullptr, 0, 0, 0, nullptr, DD, 1, 0, 0);

    // 3. scores = q @ k^T (causal blocks) -> out1 fp32 (bf16x3, precision-critical)
    {
        dim3 gS(SS_ / 128, SS_ / 128, BB * HH);
        mma_gemm<<<gS, 256, GSMEM>>>(
            Ch, Cl, DD, (long long)SS_ * DD, DH_,
            Kh, Kl, DD, (long long)SS_ * DD, DH_,
            out1, nullptr, nullptr, SS_, (long long)HH * SS_ * SS_, (long long)SS_ * SS_,
            nullptr, nullptr, 0, 0, 0, nullptr, DH_, HH, 0, 1);
    }

    // 4. softmax in place + fp16 hi/lo weights -> Ah/Al (as __half)
    {
        dim3 gA(SS_, HH, BB);
        softmax_kernel<<<gA, 256>>>(out1, (__half*)Ah, (__half*)Al);
    }

    // 5. v^T -> single fp16 Bh; ctx = weights @ v  [fp16 2-pass, batched, causal]
    {
        dim3 gVT(SS_ / 32, DH_ / 32, BB * HH);
        vtrans_kernel<<<gVT, 256>>>(v, (__half*)Bh);
        dim3 gV(DH_ / 128, SS_ / 128, BB * HH);
        mma_gemm_h<<<gV, 256, GSMEM_H>>>(
            (__half*)Ah, (__half*)Al, SS_, (long long)HH * SS_ * SS_, (long long)SS_ * SS_,
            (__half*)Bh, SS_, (long long)HH * DH_ * SS_, (long long)DH_ * SS_,
            nullptr, (__half*)Ch, (__half*)Cl, DD, (long long)SS_ * DD, DH_,
            nullptr, nullptr, 0, SS_, HH, 0, 2);
    }

    // 6. res = ctx @ wo + hidden (fp32)  [fp16 2-pass]
    wtrans_h_kernel<<<gW, 256>>>(wo, (__half*)Bh, DD, DD);
    mma_gemm_h<<<gQ, 256, GSMEM_H>>>((__half*)Ch, (__half*)Cl, DD, 0, 0,
                                     (__half*)Bh, DD, 0, 0,
                                     res, nullptr, nullptr, DD, 0, 0,
                                     nullptr, hidden, DD, DD, 1, 0, 0);

    // 7. LN2 -> h fp32 + fp16 hi/lo (Ah/Al reinterpret)
    ln_fused_kernel<<<ROWS, 256>>>(res, ln2_g, ln2_b, h, Ah, Al, 1);

    // 8. ffn = gelu(h2 @ fc_in + b) -> fp16 hi/lo Ch/Cl  [fp16 2-pass]
    {
        dim3 gW1(DD / 32, FF_ / 32);
        wtrans_h_kernel<<<gW1, 256>>>(fc_in_w, (__half*)Bh, DD, FF_);
        dim3 gF1(FF_ / 128, ROWS / 128, 1);
        mma_gemm_h<<<gF1, 256, GSMEM_H>>>((__half*)Ah, (__half*)Al, DD, 0, 0,
                                          (__half*)Bh, DD, 0, 0,
                                          nullptr, (__half*)Ch, (__half*)Cl, FF_, 0, 0,
                                          fc_in_b, nullptr, 0, DD, 1, 1, 0);
    }

    // 9. out0 = ffn @ fc_out + b + h2  [fp16 2-pass]
    {
        dim3 gW2(FF_ / 32, DD / 32);
        wtrans_h_kernel<<<gW2, 256>>>(fc_out_w, (__half*)Bh, FF_, DD);
        dim3 gF2(DD / 128, ROWS / 128, 1);
        mma_gemm_h<<<gF2, 256, GSMEM_H>>>((__half*)Ch, (__half*)Cl, FF_, 0, 0,
                                          (__half*)Bh, FF_, 0, 0,
                                          out0, nullptr, nullptr, DD, 0, 0,
                                          fc_out_b, h, DD, FF_, 1, 0, 0);
    }
}

// round 13
// speedup vs baseline: 1.4075x; 1.0467x over previous
#include <cuda_runtime.h>
#include <cuda_fp16.h>
#include <math.h>
#include <stdint.h>

// Problem dims (fixed)
#define BB 2
#define SS_ 2048
#define DD 2048
#define HH 16
#define DH_ 128
#define FF_ 8192
#define ROWS 4096            // B*S

// ---------------- scratch ----------------
__device__ float g_h   [(size_t)ROWS * DD];   // h2 (LN2 out, fp32)
__device__ float g_v   [(size_t)ROWS * DD];
__device__ float g_res [(size_t)ROWS * DD];

#define AMAX ((size_t)BB * HH * SS_ * SS_)
#define BMAX ((size_t)DD * FF_)
#define CMAX ((size_t)ROWS * FF_)
__device__ __half g_Ah[AMAX];
__device__ __half g_Al[AMAX];
__device__ __half g_Bh[BMAX];
__device__ __half g_Bl[BMAX];
__device__ __half g_Ch[CMAX];
__device__ __half g_Cl[CMAX];
__device__ __half g_Kh[(size_t)ROWS * DD];
__device__ __half g_Kl[(size_t)ROWS * DD];

__device__ __forceinline__ uint32_t smem_u32(const void* p) {
    uint32_t a;
    asm("{ .reg .u64 t; cvta.to.shared.u64 t, %1; cvt.u32.u64 %0, t; }" : "=r"(a) : "l"(p));
    return a;
}

#define LDMX4(r0, r1, r2, r3, addr) \
    asm volatile("ldmatrix.sync.aligned.m8n8.x4.shared.b16 {%0,%1,%2,%3}, [%4];" \
                 : "=r"(r0), "=r"(r1), "=r"(r2), "=r"(r3) : "r"(addr))

#define MMAH16816(c, a, b0, b1) \
    asm volatile("mma.sync.aligned.m16n8k16.row.col.f32.f16.f16.f32 " \
                 "{%0,%1,%2,%3}, {%4,%5,%6,%7}, {%8,%9}, {%0,%1,%2,%3};" \
                 : "+f"((c)[0]), "+f"((c)[1]), "+f"((c)[2]), "+f"((c)[3]) \
                 : "r"((a)[0]), "r"((a)[1]), "r"((a)[2]), "r"((a)[3]), \
                   "r"(b0), "r"(b1))

#define CP16(dst, src) \
    asm volatile("cp.async.cg.shared.global [%0], [%1], 16;" :: "r"(dst), "l"(src))
#define CP_COMMIT() asm volatile("cp.async.commit_group;" ::: "memory")
#define CP_WAIT0()  asm volatile("cp.async.wait_group 0;" ::: "memory")

__device__ __forceinline__ void decomp2h_store(__half* hp, __half* lp,
                                               long long off, float x, float y) {
    __half hx = __float2half(x);
    __half hy = __float2half(y);
    *(__half2*)(hp + off) = __halves2half2(hx, hy);
    *(__half2*)(lp + off) = __halves2half2(__float2half(x - __half2float(hx)),
                                           __float2half(y - __half2float(hy)));
}

// ===================== LayerNorm fused with fp16 hi/lo decompose =================
__global__ void ln_fused_kernel(const float* __restrict__ x,
                                const float* __restrict__ g,
                                const float* __restrict__ b,
                                float* __restrict__ out,          // may be null
                                __half* __restrict__ oh,
                                __half* __restrict__ ol) {
    __shared__ float xs[DD];
    __shared__ float red[256];
    const int row = blockIdx.x;
    const int tid = threadIdx.x;
    const float* xr = x + (long long)row * DD;

    float s = 0.f;
    for (int i = tid; i < DD; i += 256) { float t = xr[i]; xs[i] = t; s += t; }
    red[tid] = s; __syncthreads();
    for (int o = 128; o > 0; o >>= 1) { if (tid < o) red[tid] += red[tid + o]; __syncthreads(); }
    const float mean = red[0] * (1.f / DD);
    __syncthreads();

    float v = 0.f;
    for (int i = tid; i < DD; i += 256) { float d = xs[i] - mean; v += d * d; }
    red[tid] = v; __syncthreads();
    for (int o = 128; o > 0; o >>= 1) { if (tid < o) red[tid] += red[tid + o]; __syncthreads(); }
    const float rstd = rsqrtf(red[0] * (1.f / DD) + 1e-5f);

    const long long base = (long long)row * DD;
    for (int i = tid * 2; i < DD; i += 512) {
        float a0 = (xs[i] - mean) * rstd * g[i] + b[i];
        float a1 = (xs[i + 1] - mean) * rstd * g[i + 1] + b[i + 1];
        if (out) *(float2*)(out + base + i) = make_float2(a0, a1);
        decomp2h_store(oh, ol, base + i, a0, a1);
    }
}

// ===================== softmax in place + SINGLE fp16 weights ====================
__global__ void softmax_kernel(float* __restrict__ w,
                               __half* __restrict__ oh) {
    __shared__ float sc[SS_];
    __shared__ float red[256];
    const int qi = blockIdx.x, h = blockIdx.y, b = blockIdx.z;
    const int tid = threadIdx.x;
    const long long rbase = ((long long)(b * HH + h) * SS_ + qi) * SS_;
    float* wrow = w + rbase;
    const int n = qi + 1;

    float lmax = -1e30f;
    for (int j = tid; j < n; j += 256) { float t = wrow[j]; sc[j] = t; lmax = fmaxf(lmax, t); }
    red[tid] = lmax; __syncthreads();
    for (int o = 128; o > 0; o >>= 1) { if (tid < o) red[tid] = fmaxf(red[tid], red[tid + o]); __syncthreads(); }
    const float gmax = red[0];
    __syncthreads();

    float lsum = 0.f;
    for (int j = tid; j < n; j += 256) { float e = expf(sc[j] - gmax); sc[j] = e; lsum += e; }
    red[tid] = lsum; __syncthreads();
    for (int o = 128; o > 0; o >>= 1) { if (tid < o) red[tid] += red[tid + o]; __syncthreads(); }
    const float inv = 1.f / red[0];
    __syncthreads();

    for (int j = tid * 2; j < SS_; j += 512) {
        float x = (j < n) ? sc[j] * inv : 0.f;
        float y = (j + 1 < n) ? sc[j + 1] * inv : 0.f;
        *(float2*)(wrow + j) = make_float2(x, y);
        *(__half2*)(oh + rbase + j) = __halves2half2(__float2half(x), __float2half(y));
    }
}

// ===================== transpose+decompose weight [K,N] -> [N,K] (fp16 hi/lo) ====
__global__ void wtrans_h2_kernel(const float* __restrict__ w,
                                 __half* __restrict__ bh,
                                 __half* __restrict__ bl,
                                 int Kdim, int Ndim) {
    __shared__ float t[32][33];
    const int k0 = blockIdx.x * 32, n0 = blockIdx.y * 32;
    const int tx = threadIdx.x & 31, ty = threadIdx.x >> 5;
#pragma unroll
    for (int i = 0; i < 32; i += 8)
        t[ty + i][tx] = w[(long long)(k0 + ty + i) * Ndim + n0 + tx];
    __syncthreads();
#pragma unroll
    for (int i = 0; i < 32; i += 8) {
        float v = t[tx][ty + i];
        long long o = (long long)(n0 + ty + i) * Kdim + k0 + tx;
        __half h = __float2half(v);
        bh[o] = h;
        bl[o] = __float2half(v - __half2float(h));
    }
}

// ===================== transpose weight [K,N] -> [N,K] (single fp16) ============
__global__ void wtrans_h_kernel(const float* __restrict__ w,
                                __half* __restrict__ bh,
                                int Kdim, int Ndim) {
    __shared__ float t[32][33];
    const int k0 = blockIdx.x * 32, n0 = blockIdx.y * 32;
    const int tx = threadIdx.x & 31, ty = threadIdx.x >> 5;
#pragma unroll
    for (int i = 0; i < 32; i += 8)
        t[ty + i][tx] = w[(long long)(k0 + ty + i) * Ndim + n0 + tx];
    __syncthreads();
#pragma unroll
    for (int i = 0; i < 32; i += 8)
        bh[(long long)(n0 + ty + i) * Kdim + k0 + tx] = __float2half(t[tx][ty + i]);
}

// ===================== transpose V [B,S,H,DH] -> [B,H,DH,S] single fp16 ==========
__global__ void vtrans_kernel(const float* __restrict__ v,
                              __half* __restrict__ bh) {
    __shared__ float t[32][33];
    const int bh_i = blockIdx.z;
    const int b = bh_i >> 4, h = bh_i & 15;
    const int s0 = blockIdx.x * 32, d0 = blockIdx.y * 32;
    const int tx = threadIdx.x & 31, ty = threadIdx.x >> 5;
#pragma unroll
    for (int i = 0; i < 32; i += 8)
        t[ty + i][tx] = v[(((long long)b * SS_ + s0 + ty + i) * HH + h) * DH_ + d0 + tx];
    __syncthreads();
#pragma unroll
    for (int i = 0; i < 32; i += 8) {
        long long o = ((long long)bh_i * DH_ + d0 + ty + i) * SS_ + s0 + tx;
        bh[o] = __float2half(t[tx][ty + i]);
    }
}

// ===================== fp16x3 GEMM (A hi/lo x B hi/lo, 3 passes) ================
// 128x128 CTA, BK=32, 2-stage, 2 CTA/SM, 8 warps of 64x32. (q/k proj, scores)
// act: 0 none, 2 rope->Oh/Ol
// causal: 0 none, 1 skip blocks col0>row0+127
#define SA 40
#define TILEB (128 * SA * 2)
#define STAGEB (4 * TILEB)
#define GSMEM (2 * STAGEB)

__global__ __launch_bounds__(256, 2) void mma_gemm3(
        const __half* __restrict__ Ah, const __half* __restrict__ Al,
        int lda, long long sAb, long long sAhS,
        const __half* __restrict__ Bh, const __half* __restrict__ Bl,
        int ldb, long long sBb, long long sBhS,
        float* __restrict__ C,
        __half* __restrict__ Oh, __half* __restrict__ Ol,
        int ldc, long long sCb, long long sCh,
        const int* __restrict__ pos,
        int K, int Hb, int act, int causal) {
    extern __shared__ char dsm[];

    const int row0 = blockIdx.y * 128;
    const int col0 = blockIdx.x * 128;
    if (causal == 1 && col0 > row0 + 127) return;

    const int tid = threadIdx.x;
    const int warp = tid >> 5, lane = tid & 31;
    const int wm = warp >> 2, wn = warp & 3;

    const int bz = blockIdx.z;
    const int b = bz / Hb, hh = bz % Hb;
    Ah += b * sAb + hh * sAhS;
    Al += b * sAb + hh * sAhS;
    Bh += b * sBb + hh * sBhS;
    Bl += b * sBb + hh * sBhS;
    const long long cOff = b * sCb + hh * sCh;
    if (C)  C += cOff;
    if (Oh) { Oh += cOff; Ol += cOff; }

    const uint32_t u0 = smem_u32(dsm);

    float acc[4][4][4] = {};

    const int lr0 = tid >> 2, lc = (tid & 3) * 8;
    const int a_r = lane & 15, a_c = (lane >> 4) * 8;
    const int b_r = ((lane >> 4) << 3) + (lane & 7), b_c = ((lane >> 3) & 1) * 8;

    const int nch = K / 32;

    auto load_chunk = [&](int ch, int st) {
        const int kb = ch * 32;
        const uint32_t base = u0 + st * STAGEB;
#pragma unroll
        for (int p = 0; p < 2; p++) {
            const int r = lr0 + p * 64;
            const long long ga = (long long)(row0 + r) * lda + kb + lc;
            const long long gb = (long long)(col0 + r) * ldb + kb + lc;
            const uint32_t so = (uint32_t)(r * SA + lc) * 2;
            CP16(base + so,             Ah + ga);
            CP16(base + TILEB + so,     Al + ga);
            CP16(base + 2 * TILEB + so, Bh + gb);
            CP16(base + 3 * TILEB + so, Bl + gb);
        }
    };

    load_chunk(0, 0);
    CP_COMMIT();

    for (int ch = 0; ch < nch; ch++) {
        CP_WAIT0();
        __syncthreads();
        if (ch + 1 < nch) { load_chunk(ch + 1, (ch + 1) & 1); CP_COMMIT(); }

        const uint32_t base = u0 + (ch & 1) * STAGEB;
        const uint32_t uAh = base, uAl = base + TILEB;
        const uint32_t uBh = base + 2 * TILEB, uBl = base + 3 * TILEB;

#pragma unroll
        for (int ks = 0; ks < 2; ks++) {
            const int kc = ks * 16;
            uint32_t af[4][4], fbh[2][4], fbl[2][4];
#pragma unroll
            for (int nb = 0; nb < 2; nb++) {
                const uint32_t off = (uint32_t)((wn * 32 + nb * 16 + b_r) * SA + kc + b_c) * 2;
                LDMX4(fbh[nb][0], fbh[nb][1], fbh[nb][2], fbh[nb][3], uBh + off);
                LDMX4(fbl[nb][0], fbl[nb][1], fbl[nb][2], fbl[nb][3], uBl + off);
            }
#pragma unroll
            for (int mi = 0; mi < 4; mi++) {
                const uint32_t off = (uint32_t)((wm * 64 + mi * 16 + a_r) * SA + kc + a_c) * 2;
                LDMX4(af[mi][0], af[mi][1], af[mi][2], af[mi][3], uAh + off);
            }
#pragma unroll
            for (int mi = 0; mi < 4; mi++)
#pragma unroll
                for (int ni = 0; ni < 4; ni++) {
                    MMAH16816(acc[mi][ni], af[mi], fbh[ni >> 1][(ni & 1) * 2], fbh[ni >> 1][(ni & 1) * 2 + 1]);
                    MMAH16816(acc[mi][ni], af[mi], fbl[ni >> 1][(ni & 1) * 2], fbl[ni >> 1][(ni & 1) * 2 + 1]);
                }
#pragma unroll
            for (int mi = 0; mi < 4; mi++) {
                const uint32_t off = (uint32_t)((wm * 64 + mi * 16 + a_r) * SA + kc + a_c) * 2;
                LDMX4(af[mi][0], af[mi][1], af[mi][2], af[mi][3], uAl + off);
            }
#pragma unroll
            for (int mi = 0; mi < 4; mi++)
#pragma unroll
                for (int ni = 0; ni < 4; ni++)
                    MMAH16816(acc[mi][ni], af[mi], fbh[ni >> 1][(ni & 1) * 2], fbh[ni >> 1][(ni & 1) * 2 + 1]);
        }
        __syncthreads();
    }

    // epilogue
#pragma unroll
    for (int mi = 0; mi < 4; mi++) {
#pragma unroll
        for (int ni = 0; ni < 4; ni++) {
#pragma unroll
            for (int half = 0; half < 2; half++) {
                const long long r = row0 + wm * 64 + mi * 16 + (lane >> 2) + half * 8;
                const int cc = col0 + wn * 32 + ni * 8 + (lane & 3) * 2;
                float x = acc[mi][ni][half * 2];
                float y = acc[mi][ni][half * 2 + 1];
                if (act == 2) {
                    const int i = (cc & (DH_ - 1)) >> 1;
                    const float ang = (float)pos[r] * exp10f(-(float)i * (1.f / 16.f));
                    const float sn = sinf(ang), cs = cosf(ang);
                    const float nx = x * cs - y * sn;
                    y = y * cs + x * sn;
                    x = nx;
                }
                if (C) *(float2*)(C + r * ldc + cc) = make_float2(x, y);
                if (Oh) decomp2h_store(Oh, Ol, r * ldc + cc, x, y);
            }
        }
    }
}

// ===================== fp16 1/2-pass GEMM: A hi/lo (Al optional), B single ======
// Same structure. Batched + causal=2 K-limit.
// act: 1 gelu
#define STAGEB_H (3 * TILEB)
#define GSMEM_H (2 * STAGEB_H)

__global__ __launch_bounds__(256, 2) void mma_gemm_h(
        const __half* __restrict__ Ah, const __half* __restrict__ Al,
        int lda, long long sAb, long long sAhS,
        const __half* __restrict__ Bh,
        int ldb, long long sBb, long long sBhS,
        float* __restrict__ C,
        __half* __restrict__ Oh, __half* __restrict__ Ol,
        int ldc, long long sCb, long long sCh,
        const float* __restrict__ bias,
        const float* __restrict__ res, int ldr,
        int K, int Hb, int act, int causal) {
    extern __shared__ char dsm[];

    const int row0 = blockIdx.y * 128;
    const int col0 = blockIdx.x * 128;

    const int tid = threadIdx.x;
    const int warp = tid >> 5, lane = tid & 31;
    const int wm = warp >> 2, wn = warp & 3;

    const int bz = blockIdx.z;
    const int b = bz / Hb, hh = bz % Hb;
    Ah += b * sAb + hh * sAhS;
    if (Al) Al += b * sAb + hh * sAhS;
    Bh += b * sBb + hh * sBhS;
    const long long cOff = b * sCb + hh * sCh;
    if (C)  C += cOff;
    if (Oh) { Oh += cOff; Ol += cOff; }

    const uint32_t u0 = smem_u32(dsm);

    float acc[4][4][4] = {};

    const int lr0 = tid >> 2, lc = (tid & 3) * 8;
    const int a_r = lane & 15, a_c = (lane >> 4) * 8;
    const int b_r = ((lane >> 4) << 3) + (lane & 7), b_c = ((lane >> 3) & 1) * 8;

    int nch = K / 32;
    if (causal == 2) { int lim = (row0 + 128) / 32; if (lim < nch) nch = lim; }

    auto load_chunk = [&](int ch, int st) {
        const int kb = ch * 32;
        const uint32_t base = u0 + st * STAGEB_H;
#pragma unroll
        for (int p = 0; p < 2; p++) {
            const int r = lr0 + p * 64;
            const long long ga = (long long)(row0 + r) * lda + kb + lc;
            const long long gb = (long long)(col0 + r) * ldb + kb + lc;
            const uint32_t so = (uint32_t)(r * SA + lc) * 2;
            CP16(base + so,             Ah + ga);
            if (Al) CP16(base + TILEB + so, Al + ga);
            CP16(base + 2 * TILEB + so, Bh + gb);
        }
    };

    load_chunk(0, 0);
    CP_COMMIT();

    for (int ch = 0; ch < nch; ch++) {
        CP_WAIT0();
        __syncthreads();
        if (ch + 1 < nch) { load_chunk(ch + 1, (ch + 1) & 1); CP_COMMIT(); }

        const uint32_t base = u0 + (ch & 1) * STAGEB_H;
        const uint32_t uAh = base, uAl = base + TILEB;
        const uint32_t uBh = base + 2 * TILEB;

#pragma unroll
        for (int ks = 0; ks < 2; ks++) {
            const int kc = ks * 16;
            uint32_t af[4][4], fbh[2][4];
#pragma unroll
            for (int nb = 0; nb < 2; nb++) {
                const uint32_t off = (uint32_t)((wn * 32 + nb * 16 + b_r) * SA + kc + b_c) * 2;
                LDMX4(fbh[nb][0], fbh[nb][1], fbh[nb][2], fbh[nb][3], uBh + off);
            }
#pragma unroll
            for (int mi = 0; mi < 4; mi++) {
                const uint32_t off = (uint32_t)((wm * 64 + mi * 16 + a_r) * SA + kc + a_c) * 2;
                LDMX4(af[mi][0], af[mi][1], af[mi][2], af[mi][3], uAh + off);
            }
#pragma unroll
            for (int mi = 0; mi < 4; mi++)
#pragma unroll
                for (int ni = 0; ni < 4; ni++)
                    MMAH16816(acc[mi][ni], af[mi], fbh[ni >> 1][(ni & 1) * 2], fbh[ni >> 1][(ni & 1) * 2 + 1]);
            if (Al) {
#pragma unroll
                for (int mi = 0; mi < 4; mi++) {
                    const uint32_t off = (uint32_t)((wm * 64 + mi * 16 + a_r) * SA + kc + a_c) * 2;
                    LDMX4(af[mi][0], af[mi][1], af[mi][2], af[mi][3], uAl + off);
                }
#pragma unroll
                for (int mi = 0; mi < 4; mi++)
#pragma unroll
                    for (int ni = 0; ni < 4; ni++)
                        MMAH16816(acc[mi][ni], af[mi], fbh[ni >> 1][(ni & 1) * 2], fbh[ni >> 1][(ni & 1) * 2 + 1]);
            }
        }
        __syncthreads();
    }

    // epilogue
#pragma unroll
    for (int mi = 0; mi < 4; mi++) {
#pragma unroll
        for (int ni = 0; ni < 4; ni++) {
#pragma unroll
            for (int half = 0; half < 2; half++) {
                const long long r = row0 + wm * 64 + mi * 16 + (lane >> 2) + half * 8;
                const int cc = col0 + wn * 32 + ni * 8 + (lane & 3) * 2;
                float x = acc[mi][ni][half * 2];
                float y = acc[mi][ni][half * 2 + 1];
                if (bias) { x += bias[cc]; y += bias[cc + 1]; }
                if (act == 1) {
                    x = 0.5f * x * (1.f + erff(x * 0.70710678118654752f));
                    y = 0.5f * y * (1.f + erff(y * 0.70710678118654752f));
                }
                if (res) { x += res[r * ldr + cc]; y += res[r * ldr + cc + 1]; }
                if (C) *(float2*)(C + r * ldc + cc) = make_float2(x, y);
                if (Oh) decomp2h_store(Oh, Ol, r * ldc + cc, x, y);
            }
        }
    }
}

// ===================== host launch =====================
extern "C" void kernel_launch(void* const* d_in, const int* in_sizes, int n_in,
                              void* d_out, int out_size) {
    const float* hidden  = (const float*)d_in[0];
    const int*   pos     = (const int*)  d_in[1];
    const float* wq      = (const float*)d_in[2];
    const float* wk      = (const float*)d_in[3];
    const float* wv      = (const float*)d_in[4];
    const float* wo      = (const float*)d_in[5];
    const float* ln1_g   = (const float*)d_in[6];
    const float* ln1_b   = (const float*)d_in[7];
    const float* ln2_g   = (const float*)d_in[8];
    const float* ln2_b   = (const float*)d_in[9];
    const float* fc_in_w = (const float*)d_in[10];
    const float* fc_in_b = (const float*)d_in[11];
    const float* fc_out_w= (const float*)d_in[12];
    const float* fc_out_b= (const float*)d_in[13];

    float* out0 = (float*)d_out;                               // [B,S,D]
    float* out1 = out0 + (long long)BB * SS_ * DD;             // [B,H,S,S]

    float *h, *v, *res;
    __half *Ah, *Al, *Bh, *Bl, *Ch, *Cl, *Kh, *Kl;
    cudaGetSymbolAddress((void**)&h,   g_h);
    cudaGetSymbolAddress((void**)&v,   g_v);
    cudaGetSymbolAddress((void**)&res, g_res);
    cudaGetSymbolAddress((void**)&Ah,  g_Ah);
    cudaGetSymbolAddress((void**)&Al,  g_Al);
    cudaGetSymbolAddress((void**)&Bh,  g_Bh);
    cudaGetSymbolAddress((void**)&Bl,  g_Bl);
    cudaGetSymbolAddress((void**)&Ch,  g_Ch);
    cudaGetSymbolAddress((void**)&Cl,  g_Cl);
    cudaGetSymbolAddress((void**)&Kh,  g_Kh);
    cudaGetSymbolAddress((void**)&Kl,  g_Kl);

    cudaFuncSetAttribute(mma_gemm3,  cudaFuncAttributeMaxDynamicSharedMemorySize, GSMEM);
    cudaFuncSetAttribute(mma_gemm_h, cudaFuncAttributeMaxDynamicSharedMemorySize, GSMEM_H);

    // 1. LN1 -> fp16 hi/lo
    ln_fused_kernel<<<ROWS, 256>>>(hidden, ln1_g, ln1_b, nullptr, Ah, Al);

    // 2. QKV: q,k via fp16x3 + fused RoPE -> hi/lo; v via fp16 2-pass -> fp32
    dim3 gQ(DD / 128, ROWS / 128, 1);
    dim3 gW(DD / 32, DD / 32);
    wtrans_h2_kernel<<<gW, 256>>>(wq, Bh, Bl, DD, DD);
    mma_gemm3<<<gQ, 256, GSMEM>>>(Ah, Al, DD, 0, 0, Bh, Bl, DD, 0, 0,
                                  nullptr, Ch, Cl, DD, 0, 0, pos, DD, 1, 2, 0);
    wtrans_h2_kernel<<<gW, 256>>>(wk, Bh, Bl, DD, DD);
    mma_gemm3<<<gQ, 256, GSMEM>>>(Ah, Al, DD, 0, 0, Bh, Bl, DD, 0, 0,
                                  nullptr, Kh, Kl, DD, 0, 0, pos, DD, 1, 2, 0);
    wtrans_h_kernel<<<gW, 256>>>(wv, Bh, DD, DD);
    mma_gemm_h<<<gQ, 256, GSMEM_H>>>(Ah, Al, DD, 0, 0, Bh, DD, 0, 0,
                                     v, nullptr, nullptr, DD, 0, 0,
                                     nullptr, nullptr, 0, DD, 1, 0, 0);

    // 3. scores = q @ k^T (causal blocks) -> out1 fp32 (fp16x3)
    {
        dim3 gS(SS_ / 128, SS_ / 128, BB * HH);
        mma_gemm3<<<gS, 256, GSMEM>>>(
            Ch, Cl, DD, (long long)SS_ * DD, DH_,
            Kh, Kl, DD, (long long)SS_ * DD, DH_,
            out1, nullptr, nullptr, SS_, (long long)HH * SS_ * SS_, (long long)SS_ * SS_,
            nullptr, DH_, HH, 0, 1);
    }

    // 4. softmax in place + single fp16 weights -> Ah
    {
        dim3 gA(SS_, HH, BB);
        softmax_kernel<<<gA, 256>>>(out1, Ah);
    }

    // 5. v^T -> single fp16 Bh; ctx = weights @ v  [fp16 1-pass, batched, causal]
    {
        dim3 gVT(SS_ / 32, DH_ / 32, BB * HH);
        vtrans_kernel<<<gVT, 256>>>(v, Bh);
        dim3 gV(DH_ / 128, SS_ / 128, BB * HH);
        mma_gemm_h<<<gV, 256, GSMEM_H>>>(
            Ah, nullptr, SS_, (long long)HH * SS_ * SS_, (long long)SS_ * SS_,
            Bh, SS_, (long long)HH * DH_ * SS_, (long long)DH_ * SS_,
            nullptr, Ch, Cl, DD, (long long)SS_ * DD, DH_,
            nullptr, nullptr, 0, SS_, HH, 0, 2);
    }

    // 6. res = ctx @ wo + hidden (fp32)  [fp16 2-pass]
    wtrans_h_kernel<<<gW, 256>>>(wo, Bh, DD, DD);
    mma_gemm_h<<<gQ, 256, GSMEM_H>>>(Ch, Cl, DD, 0, 0, Bh, DD, 0, 0,
                                     res, nullptr, nullptr, DD, 0, 0,
                                     nullptr, hidden, DD, DD, 1, 0, 0);

    // 7. LN2 -> h fp32 + fp16 hi/lo
    ln_fused_kernel<<<ROWS, 256>>>(res, ln2_g, ln2_b, h, Ah, Al);

    // 8. ffn = gelu(h2 @ fc_in + b) -> fp16 hi/lo Ch/Cl  [fp16 2-pass]
    {
        dim3 gW1(DD / 32, FF_ / 32);
        wtrans_h_kernel<<<gW1, 256>>>(fc_in_w, Bh, DD, FF_);
        dim3 gF1(FF_ / 128, ROWS / 128, 1);
        mma_gemm_h<<<gF1, 256, GSMEM_H>>>(Ah, Al, DD, 0, 0, Bh, DD, 0, 0,
                                          nullptr, Ch, Cl, FF_, 0, 0,
                                          fc_in_b, nullptr, 0, DD, 1, 1, 0);
    }

    // 9. out0 = ffn @ fc_out + b + h2  [fp16 2-pass]
    {
        dim3 gW2(FF_ / 32, DD / 32);
        wtrans_h_kernel<<<gW2, 256>>>(fc_out_w, Bh, FF_, DD);
        dim3 gF2(DD / 128, ROWS / 128, 1);
        mma_gemm_h<<<gF2, 256, GSMEM_H>>>(Ch, Cl, FF_, 0, 0, Bh, FF_, 0, 0,
                                          out0, nullptr, nullptr, DD, 0, 0,
                                          fc_out_b, h, DD, FF_, 1, 0, 0);
    }
}

// round 15
// speedup vs baseline: 1.5168x; 1.0777x over previous
#include <cuda_runtime.h>
#include <cuda_fp16.h>
#include <math.h>
#include <stdint.h>

// Problem dims (fixed)
#define BB 2
#define SS_ 2048
#define DD 2048
#define HH 16
#define DH_ 128
#define FF_ 8192
#define ROWS 4096            // B*S

// ---------------- scratch ----------------
__device__ float g_h   [(size_t)ROWS * DD];   // h2 (LN2 out, fp32)
__device__ float g_v   [(size_t)ROWS * DD];
__device__ float g_res [(size_t)ROWS * DD];

#define AMAX ((size_t)BB * HH * SS_ * SS_)
#define BMAX ((size_t)DD * FF_)
#define CMAX ((size_t)ROWS * FF_)
__device__ __half g_Ah[AMAX];
__device__ __half g_Al[AMAX];
__device__ __half g_Bh[BMAX];
__device__ __half g_Bl[BMAX];
__device__ __half g_Ch[CMAX];
__device__ __half g_Cl[CMAX];
__device__ __half g_Kh[(size_t)ROWS * DD];
__device__ __half g_Kl[(size_t)ROWS * DD];

__device__ __forceinline__ uint32_t smem_u32(const void* p) {
    uint32_t a;
    asm("{ .reg .u64 t; cvta.to.shared.u64 t, %1; cvt.u32.u64 %0, t; }" : "=r"(a) : "l"(p));
    return a;
}

#define LDMX4(r0, r1, r2, r3, addr) \
    asm volatile("ldmatrix.sync.aligned.m8n8.x4.shared.b16 {%0,%1,%2,%3}, [%4];" \
                 : "=r"(r0), "=r"(r1), "=r"(r2), "=r"(r3) : "r"(addr))

#define MMAH16816(c, a, b0, b1) \
    asm volatile("mma.sync.aligned.m16n8k16.row.col.f32.f16.f16.f32 " \
                 "{%0,%1,%2,%3}, {%4,%5,%6,%7}, {%8,%9}, {%0,%1,%2,%3};" \
                 : "+f"((c)[0]), "+f"((c)[1]), "+f"((c)[2]), "+f"((c)[3]) \
                 : "r"((a)[0]), "r"((a)[1]), "r"((a)[2]), "r"((a)[3]), \
                   "r"(b0), "r"(b1))

#define CP16(dst, src) \
    asm volatile("cp.async.cg.shared.global [%0], [%1], 16;" :: "r"(dst), "l"(src))
#define CP_COMMIT() asm volatile("cp.async.commit_group;" ::: "memory")
#define CP_WAIT0()  asm volatile("cp.async.wait_group 0;" ::: "memory")

__device__ __forceinline__ void decomp2h_store(__half* hp, __half* lp,
                                               long long off, float x, float y) {
    __half hx = __float2half(x);
    __half hy = __float2half(y);
    *(__half2*)(hp + off) = __halves2half2(hx, hy);
    *(__half2*)(lp + off) = __halves2half2(__float2half(x - __half2float(hx)),
                                           __float2half(y - __half2float(hy)));
}

// ===================== LayerNorm fused with fp16 hi/lo decompose =================
__global__ void ln_fused_kernel(const float* __restrict__ x,
                                const float* __restrict__ g,
                                const float* __restrict__ b,
                                float* __restrict__ out,          // may be null
                                __half* __restrict__ oh,
                                __half* __restrict__ ol) {
    __shared__ float xs[DD];
    __shared__ float red[256];
    const int row = blockIdx.x;
    const int tid = threadIdx.x;
    const float* xr = x + (long long)row * DD;

    float s = 0.f;
    for (int i = tid; i < DD; i += 256) { float t = xr[i]; xs[i] = t; s += t; }
    red[tid] = s; __syncthreads();
    for (int o = 128; o > 0; o >>= 1) { if (tid < o) red[tid] += red[tid + o]; __syncthreads(); }
    const float mean = red[0] * (1.f / DD);
    __syncthreads();

    float v = 0.f;
    for (int i = tid; i < DD; i += 256) { float d = xs[i] - mean; v += d * d; }
    red[tid] = v; __syncthreads();
    for (int o = 128; o > 0; o >>= 1) { if (tid < o) red[tid] += red[tid + o]; __syncthreads(); }
    const float rstd = rsqrtf(red[0] * (1.f / DD) + 1e-5f);

    const long long base = (long long)row * DD;
    for (int i = tid * 2; i < DD; i += 512) {
        float a0 = (xs[i] - mean) * rstd * g[i] + b[i];
        float a1 = (xs[i + 1] - mean) * rstd * g[i + 1] + b[i + 1];
        if (out) *(float2*)(out + base + i) = make_float2(a0, a1);
        decomp2h_store(oh, ol, base + i, a0, a1);
    }
}

// ===================== softmax in place + SINGLE fp16 weights ====================
__global__ void softmax_kernel(float* __restrict__ w,
                               __half* __restrict__ oh) {
    __shared__ float sc[SS_];
    __shared__ float red[256];
    const int qi = blockIdx.x, h = blockIdx.y, b = blockIdx.z;
    const int tid = threadIdx.x;
    const long long rbase = ((long long)(b * HH + h) * SS_ + qi) * SS_;
    float* wrow = w + rbase;
    const int n = qi + 1;

    float lmax = -1e30f;
    for (int j = tid; j < n; j += 256) { float t = wrow[j]; sc[j] = t; lmax = fmaxf(lmax, t); }
    red[tid] = lmax; __syncthreads();
    for (int o = 128; o > 0; o >>= 1) { if (tid < o) red[tid] = fmaxf(red[tid], red[tid + o]); __syncthreads(); }
    const float gmax = red[0];
    __syncthreads();

    float lsum = 0.f;
    for (int j = tid; j < n; j += 256) { float e = expf(sc[j] - gmax); sc[j] = e; lsum += e; }
    red[tid] = lsum; __syncthreads();
    for (int o = 128; o > 0; o >>= 1) { if (tid < o) red[tid] += red[tid + o]; __syncthreads(); }
    const float inv = 1.f / red[0];
    __syncthreads();

    for (int j = tid * 2; j < SS_; j += 512) {
        float x = (j < n) ? sc[j] * inv : 0.f;
        float y = (j + 1 < n) ? sc[j + 1] * inv : 0.f;
        *(float2*)(wrow + j) = make_float2(x, y);
        *(__half2*)(oh + rbase + j) = __halves2half2(__float2half(x), __float2half(y));
    }
}

// ===================== transpose+decompose weight [K,N] -> [N,K] (fp16 hi/lo) ====
__global__ void wtrans_h2_kernel(const float* __restrict__ w,
                                 __half* __restrict__ bh,
                                 __half* __restrict__ bl,
                                 int Kdim, int Ndim) {
    __shared__ float t[32][33];
    const int k0 = blockIdx.x * 32, n0 = blockIdx.y * 32;
    const int tx = threadIdx.x & 31, ty = threadIdx.x >> 5;
#pragma unroll
    for (int i = 0; i < 32; i += 8)
        t[ty + i][tx] = w[(long long)(k0 + ty + i) * Ndim + n0 + tx];
    __syncthreads();
#pragma unroll
    for (int i = 0; i < 32; i += 8) {
        float v = t[tx][ty + i];
        long long o = (long long)(n0 + ty + i) * Kdim + k0 + tx;
        __half h = __float2half(v);
        bh[o] = h;
        bl[o] = __float2half(v - __half2float(h));
    }
}

// ===================== transpose weight [K,N] -> [N,K] (single fp16) ============
__global__ void wtrans_h_kernel(const float* __restrict__ w,
                                __half* __restrict__ bh,
                                int Kdim, int Ndim) {
    __shared__ float t[32][33];
    const int k0 = blockIdx.x * 32, n0 = blockIdx.y * 32;
    const int tx = threadIdx.x & 31, ty = threadIdx.x >> 5;
#pragma unroll
    for (int i = 0; i < 32; i += 8)
        t[ty + i][tx] = w[(long long)(k0 + ty + i) * Ndim + n0 + tx];
    __syncthreads();
#pragma unroll
    for (int i = 0; i < 32; i += 8)
        bh[(long long)(n0 + ty + i) * Kdim + k0 + tx] = __float2half(t[tx][ty + i]);
}

// ===================== transpose V [B,S,H,DH] -> [B,H,DH,S] single fp16 ==========
__global__ void vtrans_kernel(const float* __restrict__ v,
                              __half* __restrict__ bh) {
    __shared__ float t[32][33];
    const int bh_i = blockIdx.z;
    const int b = bh_i >> 4, h = bh_i & 15;
    const int s0 = blockIdx.x * 32, d0 = blockIdx.y * 32;
    const int tx = threadIdx.x & 31, ty = threadIdx.x >> 5;
#pragma unroll
    for (int i = 0; i < 32; i += 8)
        t[ty + i][tx] = v[(((long long)b * SS_ + s0 + ty + i) * HH + h) * DH_ + d0 + tx];
    __syncthreads();
#pragma unroll
    for (int i = 0; i < 32; i += 8) {
        long long o = ((long long)bh_i * DH_ + d0 + ty + i) * SS_ + s0 + tx;
        bh[o] = __float2half(t[tx][ty + i]);
    }
}

// ===================== fp16x3 GEMM (A hi/lo x B hi/lo, 3 passes) ================
// 128x128 CTA, BK=32, 2-stage, 2 CTA/SM, 8 warps of 64x32. (q/k proj, scores)
// act: 0 none, 2 rope->Oh/Ol ; causal: 0 none, 1 skip blocks col0>row0+127
#define SA 40
#define TILEB (128 * SA * 2)
#define STAGEB (4 * TILEB)
#define GSMEM (2 * STAGEB)

__global__ __launch_bounds__(256, 2) void mma_gemm3(
        const __half* __restrict__ Ah, const __half* __restrict__ Al,
        int lda, long long sAb, long long sAhS,
        const __half* __restrict__ Bh, const __half* __restrict__ Bl,
        int ldb, long long sBb, long long sBhS,
        float* __restrict__ C,
        __half* __restrict__ Oh, __half* __restrict__ Ol,
        int ldc, long long sCb, long long sCh,
        const int* __restrict__ pos,
        int K, int Hb, int act, int causal) {
    extern __shared__ char dsm[];

    const int row0 = blockIdx.y * 128;
    const int col0 = blockIdx.x * 128;
    if (causal == 1 && col0 > row0 + 127) return;

    const int tid = threadIdx.x;
    const int warp = tid >> 5, lane = tid & 31;
    const int wm = warp >> 2, wn = warp & 3;

    const int bz = blockIdx.z;
    const int b = bz / Hb, hh = bz % Hb;
    Ah += b * sAb + hh * sAhS;
    Al += b * sAb + hh * sAhS;
    Bh += b * sBb + hh * sBhS;
    Bl += b * sBb + hh * sBhS;
    const long long cOff = b * sCb + hh * sCh;
    if (C)  C += cOff;
    if (Oh) { Oh += cOff; Ol += cOff; }

    const uint32_t u0 = smem_u32(dsm);

    float acc[4][4][4] = {};

    const int lr0 = tid >> 2, lc = (tid & 3) * 8;
    const int a_r = lane & 15, a_c = (lane >> 4) * 8;
    const int b_r = ((lane >> 4) << 3) + (lane & 7), b_c = ((lane >> 3) & 1) * 8;

    const int nch = K / 32;

    auto load_chunk = [&](int ch, int st) {
        const int kb = ch * 32;
        const uint32_t base = u0 + st * STAGEB;
#pragma unroll
        for (int p = 0; p < 2; p++) {
            const int r = lr0 + p * 64;
            const long long ga = (long long)(row0 + r) * lda + kb + lc;
            const long long gb = (long long)(col0 + r) * ldb + kb + lc;
            const uint32_t so = (uint32_t)(r * SA + lc) * 2;
            CP16(base + so,             Ah + ga);
            CP16(base + TILEB + so,     Al + ga);
            CP16(base + 2 * TILEB + so, Bh + gb);
            CP16(base + 3 * TILEB + so, Bl + gb);
        }
    };

    load_chunk(0, 0);
    CP_COMMIT();

    for (int ch = 0; ch < nch; ch++) {
        CP_WAIT0();
        __syncthreads();
        if (ch + 1 < nch) { load_chunk(ch + 1, (ch + 1) & 1); CP_COMMIT(); }

        const uint32_t base = u0 + (ch & 1) * STAGEB;
        const uint32_t uAh = base, uAl = base + TILEB;
        const uint32_t uBh = base + 2 * TILEB, uBl = base + 3 * TILEB;

#pragma unroll
        for (int ks = 0; ks < 2; ks++) {
            const int kc = ks * 16;
            uint32_t af[4][4], fbh[2][4], fbl[2][4];
#pragma unroll
            for (int nb = 0; nb < 2; nb++) {
                const uint32_t off = (uint32_t)((wn * 32 + nb * 16 + b_r) * SA + kc + b_c) * 2;
                LDMX4(fbh[nb][0], fbh[nb][1], fbh[nb][2], fbh[nb][3], uBh + off);
                LDMX4(fbl[nb][0], fbl[nb][1], fbl[nb][2], fbl[nb][3], uBl + off);
            }
#pragma unroll
            for (int mi = 0; mi < 4; mi++) {
                const uint32_t off = (uint32_t)((wm * 64 + mi * 16 + a_r) * SA + kc + a_c) * 2;
                LDMX4(af[mi][0], af[mi][1], af[mi][2], af[mi][3], uAh + off);
            }
#pragma unroll
            for (int mi = 0; mi < 4; mi++)
#pragma unroll
                for (int ni = 0; ni < 4; ni++) {
                    MMAH16816(acc[mi][ni], af[mi], fbh[ni >> 1][(ni & 1) * 2], fbh[ni >> 1][(ni & 1) * 2 + 1]);
                    MMAH16816(acc[mi][ni], af[mi], fbl[ni >> 1][(ni & 1) * 2], fbl[ni >> 1][(ni & 1) * 2 + 1]);
                }
#pragma unroll
            for (int mi = 0; mi < 4; mi++) {
                const uint32_t off = (uint32_t)((wm * 64 + mi * 16 + a_r) * SA + kc + a_c) * 2;
                LDMX4(af[mi][0], af[mi][1], af[mi][2], af[mi][3], uAl + off);
            }
#pragma unroll
            for (int mi = 0; mi < 4; mi++)
#pragma unroll
                for (int ni = 0; ni < 4; ni++)
                    MMAH16816(acc[mi][ni], af[mi], fbh[ni >> 1][(ni & 1) * 2], fbh[ni >> 1][(ni & 1) * 2 + 1]);
        }
        __syncthreads();
    }

    // epilogue
#pragma unroll
    for (int mi = 0; mi < 4; mi++) {
#pragma unroll
        for (int ni = 0; ni < 4; ni++) {
#pragma unroll
            for (int half = 0; half < 2; half++) {
                const long long r = row0 + wm * 64 + mi * 16 + (lane >> 2) + half * 8;
                const int cc = col0 + wn * 32 + ni * 8 + (lane & 3) * 2;
                float x = acc[mi][ni][half * 2];
                float y = acc[mi][ni][half * 2 + 1];
                if (act == 2) {
                    const int i = (cc & (DH_ - 1)) >> 1;
                    const float ang = (float)pos[r] * exp10f(-(float)i * (1.f / 16.f));
                    const float sn = sinf(ang), cs = cosf(ang);
                    const float nx = x * cs - y * sn;
                    y = y * cs + x * sn;
                    x = nx;
                }
                if (C) *(float2*)(C + r * ldc + cc) = make_float2(x, y);
                if (Oh) decomp2h_store(Oh, Ol, r * ldc + cc, x, y);
            }
        }
    }
}

// ===================== fp16 1/2-pass GEMM, BK=64, 2-stage, 2 CTA/SM =============
// A hi/lo (Al optional), B single fp16. Batched + causal=2 K-limit. act: 1 gelu
#define SAH 72
#define HTILE (128 * SAH * 2)        // 18432
#define STAGEB_H (3 * HTILE)         // 55296
#define GSMEM_H (2 * STAGEB_H)       // 110592

__global__ __launch_bounds__(256, 2) void mma_gemm_h(
        const __half* __restrict__ Ah, const __half* __restrict__ Al,
        int lda, long long sAb, long long sAhS,
        const __half* __restrict__ Bh,
        int ldb, long long sBb, long long sBhS,
        float* __restrict__ C,
        __half* __restrict__ Oh, __half* __restrict__ Ol,
        int ldc, long long sCb, long long sCh,
        const float* __restrict__ bias,
        const float* __restrict__ res, int ldr,
        int K, int Hb, int act, int causal) {
    extern __shared__ char dsm[];

    const int row0 = blockIdx.y * 128;
    const int col0 = blockIdx.x * 128;

    const int tid = threadIdx.x;
    const int warp = tid >> 5, lane = tid & 31;
    const int wm = warp >> 2, wn = warp & 3;

    const int bz = blockIdx.z;
    const int b = bz / Hb, hh = bz % Hb;
    Ah += b * sAb + hh * sAhS;
    if (Al) Al += b * sAb + hh * sAhS;
    Bh += b * sBb + hh * sBhS;
    const long long cOff = b * sCb + hh * sCh;
    if (C)  C += cOff;
    if (Oh) { Oh += cOff; Ol += cOff; }

    const uint32_t u0 = smem_u32(dsm);

    float acc[4][4][4] = {};

    const int lr0 = tid >> 3, lc = (tid & 7) * 8;   // 32 rows per pass, 64 cols
    const int a_r = lane & 15, a_c = (lane >> 4) * 8;
    const int b_r = ((lane >> 4) << 3) + (lane & 7), b_c = ((lane >> 3) & 1) * 8;

    int nch = K / 64;
    if (causal == 2) { int lim = (row0 + 128) / 64; if (lim < nch) nch = lim; }

    auto load_chunk = [&](int ch, int st) {
        const int kb = ch * 64;
        const uint32_t base = u0 + st * STAGEB_H;
#pragma unroll
        for (int p = 0; p < 4; p++) {
            const int r = lr0 + p * 32;
            const long long ga = (long long)(row0 + r) * lda + kb + lc;
            const long long gb = (long long)(col0 + r) * ldb + kb + lc;
            const uint32_t so = (uint32_t)(r * SAH + lc) * 2;
            CP16(base + so, Ah + ga);
            if (Al) CP16(base + HTILE + so, Al + ga);
            CP16(base + 2 * HTILE + so, Bh + gb);
        }
    };

    load_chunk(0, 0);
    CP_COMMIT();

    for (int ch = 0; ch < nch; ch++) {
        CP_WAIT0();
        __syncthreads();
        if (ch + 1 < nch) { load_chunk(ch + 1, (ch + 1) & 1); CP_COMMIT(); }

        const uint32_t base = u0 + (ch & 1) * STAGEB_H;
        const uint32_t uAh = base, uAl = base + HTILE;
        const uint32_t uBh = base + 2 * HTILE;

#pragma unroll
        for (int ks = 0; ks < 4; ks++) {
            const int kc = ks * 16;
            uint32_t af[4][4], fbh[2][4];
#pragma unroll
            for (int nb = 0; nb < 2; nb++) {
                const uint32_t off = (uint32_t)((wn * 32 + nb * 16 + b_r) * SAH + kc + b_c) * 2;
                LDMX4(fbh[nb][0], fbh[nb][1], fbh[nb][2], fbh[nb][3], uBh + off);
            }
#pragma unroll
            for (int mi = 0; mi < 4; mi++) {
                const uint32_t off = (uint32_t)((wm * 64 + mi * 16 + a_r) * SAH + kc + a_c) * 2;
                LDMX4(af[mi][0], af[mi][1], af[mi][2], af[mi][3], uAh + off);
            }
#pragma unroll
            for (int mi = 0; mi < 4; mi++)
#pragma unroll
                for (int ni = 0; ni < 4; ni++)
                    MMAH16816(acc[mi][ni], af[mi], fbh[ni >> 1][(ni & 1) * 2], fbh[ni >> 1][(ni & 1) * 2 + 1]);
            if (Al) {
#pragma unroll
                for (int mi = 0; mi < 4; mi++) {
                    const uint32_t off = (uint32_t)((wm * 64 + mi * 16 + a_r) * SAH + kc + a_c) * 2;
                    LDMX4(af[mi][0], af[mi][1], af[mi][2], af[mi][3], uAl + off);
                }
#pragma unroll
                for (int mi = 0; mi < 4; mi++)
#pragma unroll
                    for (int ni = 0; ni < 4; ni++)
                        MMAH16816(acc[mi][ni], af[mi], fbh[ni >> 1][(ni & 1) * 2], fbh[ni >> 1][(ni & 1) * 2 + 1]);
            }
        }
        __syncthreads();
    }

    // epilogue
#pragma unroll
    for (int mi = 0; mi < 4; mi++) {
#pragma unroll
        for (int ni = 0; ni < 4; ni++) {
#pragma unroll
            for (int half = 0; half < 2; half++) {
                const long long r = row0 + wm * 64 + mi * 16 + (lane >> 2) + half * 8;
                const int cc = col0 + wn * 32 + ni * 8 + (lane & 3) * 2;
                float x = acc[mi][ni][half * 2];
                float y = acc[mi][ni][half * 2 + 1];
                if (bias) { x += bias[cc]; y += bias[cc + 1]; }
                if (act == 1) {
                    x = 0.5f * x * (1.f + erff(x * 0.70710678118654752f));
                    y = 0.5f * y * (1.f + erff(y * 0.70710678118654752f));
                }
                if (res) { x += res[r * ldr + cc]; y += res[r * ldr + cc + 1]; }
                if (C) *(float2*)(C + r * ldc + cc) = make_float2(x, y);
                if (Oh) decomp2h_store(Oh, Ol, r * ldc + cc, x, y);
            }
        }
    }
}

// ===================== host launch =====================
extern "C" void kernel_launch(void* const* d_in, const int* in_sizes, int n_in,
                              void* d_out, int out_size) {
    const float* hidden  = (const float*)d_in[0];
    const int*   pos     = (const int*)  d_in[1];
    const float* wq      = (const float*)d_in[2];
    const float* wk      = (const float*)d_in[3];
    const float* wv      = (const float*)d_in[4];
    const float* wo      = (const float*)d_in[5];
    const float* ln1_g   = (const float*)d_in[6];
    const float* ln1_b   = (const float*)d_in[7];
    const float* ln2_g   = (const float*)d_in[8];
    const float* ln2_b   = (const float*)d_in[9];
    const float* fc_in_w = (const float*)d_in[10];
    const float* fc_in_b = (const float*)d_in[11];
    const float* fc_out_w= (const float*)d_in[12];
    const float* fc_out_b= (const float*)d_in[13];

    float* out0 = (float*)d_out;                               // [B,S,D]
    float* out1 = out0 + (long long)BB * SS_ * DD;             // [B,H,S,S]

    float *h, *v, *res;
    __half *Ah, *Al, *Bh, *Bl, *Ch, *Cl, *Kh, *Kl;
    cudaGetSymbolAddress((void**)&h,   g_h);
    cudaGetSymbolAddress((void**)&v,   g_v);
    cudaGetSymbolAddress((void**)&res, g_res);
    cudaGetSymbolAddress((void**)&Ah,  g_Ah);
    cudaGetSymbolAddress((void**)&Al,  g_Al);
    cudaGetSymbolAddress((void**)&Bh,  g_Bh);
    cudaGetSymbolAddress((void**)&Bl,  g_Bl);
    cudaGetSymbolAddress((void**)&Ch,  g_Ch);
    cudaGetSymbolAddress((void**)&Cl,  g_Cl);
    cudaGetSymbolAddress((void**)&Kh,  g_Kh);
    cudaGetSymbolAddress((void**)&Kl,  g_Kl);

    cudaFuncSetAttribute(mma_gemm3,  cudaFuncAttributeMaxDynamicSharedMemorySize, GSMEM);
    cudaFuncSetAttribute(mma_gemm_h, cudaFuncAttributeMaxDynamicSharedMemorySize, GSMEM_H);

    // 1. LN1 -> fp16 hi/lo
    ln_fused_kernel<<<ROWS, 256>>>(hidden, ln1_g, ln1_b, nullptr, Ah, Al);

    // 2. QKV: q,k via fp16x3 + fused RoPE -> hi/lo; v via fp16 2-pass -> fp32
    dim3 gQ(DD / 128, ROWS / 128, 1);
    dim3 gW(DD / 32, DD / 32);
    wtrans_h2_kernel<<<gW, 256>>>(wq, Bh, Bl, DD, DD);
    mma_gemm3<<<gQ, 256, GSMEM>>>(Ah, Al, DD, 0, 0, Bh, Bl, DD, 0, 0,
                                  nullptr, Ch, Cl, DD, 0, 0, pos, DD, 1, 2, 0);
    wtrans_h2_kernel<<<gW, 256>>>(wk, Bh, Bl, DD, DD);
    mma_gemm3<<<gQ, 256, GSMEM>>>(Ah, Al, DD, 0, 0, Bh, Bl, DD, 0, 0,
                                  nullptr, Kh, Kl, DD, 0, 0, pos, DD, 1, 2, 0);
    wtrans_h_kernel<<<gW, 256>>>(wv, Bh, DD, DD);
    mma_gemm_h<<<gQ, 256, GSMEM_H>>>(Ah, Al, DD, 0, 0, Bh, DD, 0, 0,
                                     v, nullptr, nullptr, DD, 0, 0,
                                     nullptr, nullptr, 0, DD, 1, 0, 0);

    // 3. scores = q @ k^T (causal blocks) -> out1 fp32 (fp16x3)
    {
        dim3 gS(SS_ / 128, SS_ / 128, BB * HH);
        mma_gemm3<<<gS, 256, GSMEM>>>(
            Ch, Cl, DD, (long long)SS_ * DD, DH_,
            Kh, Kl, DD, (long long)SS_ * DD, DH_,
            out1, nullptr, nullptr, SS_, (long long)HH * SS_ * SS_, (long long)SS_ * SS_,
            nullptr, DH_, HH, 0, 1);
    }

    // 4. softmax in place + single fp16 weights -> Ah
    {
        dim3 gA(SS_, HH, BB);
        softmax_kernel<<<gA, 256>>>(out1, Ah);
    }

    // 5. v^T -> single fp16 Bh; ctx = weights @ v  [fp16 1-pass, batched, causal]
    {
        dim3 gVT(SS_ / 32, DH_ / 32, BB * HH);
        vtrans_kernel<<<gVT, 256>>>(v, Bh);
        dim3 gV(DH_ / 128, SS_ / 128, BB * HH);
        mma_gemm_h<<<gV, 256, GSMEM_H>>>(
            Ah, nullptr, SS_, (long long)HH * SS_ * SS_, (long long)SS_ * SS_,
            Bh, SS_, (long long)HH * DH_ * SS_, (long long)DH_ * SS_,
            nullptr, Ch, Cl, DD, (long long)SS_ * DD, DH_,
            nullptr, nullptr, 0, SS_, HH, 0, 2);
    }

    // 6. res = ctx @ wo + hidden (fp32)  [fp16 2-pass]
    wtrans_h_kernel<<<gW, 256>>>(wo, Bh, DD, DD);
    mma_gemm_h<<<gQ, 256, GSMEM_H>>>(Ch, Cl, DD, 0, 0, Bh, DD, 0, 0,
                                     res, nullptr, nullptr, DD, 0, 0,
                                     nullptr, hidden, DD, DD, 1, 0, 0);

    // 7. LN2 -> h fp32 + fp16 hi/lo
    ln_fused_kernel<<<ROWS, 256>>>(res, ln2_g, ln2_b, h, Ah, Al);

    // 8. ffn = gelu(h2 @ fc_in + b) -> fp16 hi/lo Ch/Cl  [fp16 2-pass]
    {
        dim3 gW1(DD / 32, FF_ / 32);
        wtrans_h_kernel<<<gW1, 256>>>(fc_in_w, Bh, DD, FF_);
        dim3 gF1(FF_ / 128, ROWS / 128, 1);
        mma_gemm_h<<<gF1, 256, GSMEM_H>>>(Ah, Al, DD, 0, 0, Bh, DD, 0, 0,
                                          nullptr, Ch, Cl, FF_, 0, 0,
                                          fc_in_b, nullptr, 0, DD, 1, 1, 0);
    }

    // 9. out0 = ffn @ fc_out + b + h2  [fp16 2-pass]
    {
        dim3 gW2(FF_ / 32, DD / 32);
        wtrans_h_kernel<<<gW2, 256>>>(fc_out_w, Bh, FF_, DD);
        dim3 gF2(DD / 128, ROWS / 128, 1);
        mma_gemm_h<<<gF2, 256, GSMEM_H>>>(Ch, Cl, FF_, 0, 0, Bh, FF_, 0, 0,
                                          out0, nullptr, nullptr, DD, 0, 0,
                                          fc_out_b, h, DD, FF_, 1, 0, 0);
    }
}

// round 16
// speedup vs baseline: 2.0415x; 1.3460x over previous
#include <cuda_runtime.h>
#include <cuda_fp16.h>
#include <math.h>
#include <stdint.h>

// Problem dims (fixed)
#define BB 2
#define SS_ 2048
#define DD 2048
#define HH 16
#define DH_ 128
#define FF_ 8192
#define ROWS 4096            // B*S

// ---------------- scratch ----------------
__device__ float g_h   [(size_t)ROWS * DD];   // h2 (LN2 out, fp32)
__device__ float g_v   [(size_t)ROWS * DD];
__device__ float g_res [(size_t)ROWS * DD];

#define AMAX ((size_t)BB * HH * SS_ * SS_)
#define BMAX ((size_t)DD * FF_)
#define CMAX ((size_t)ROWS * FF_)
__device__ __half g_Ah[AMAX];
__device__ __half g_Al[AMAX];
__device__ __half g_Bh[BMAX];
__device__ __half g_Bl[BMAX];
__device__ __half g_Ch[CMAX];
__device__ __half g_Cl[CMAX];
__device__ __half g_Kh[(size_t)ROWS * DD];
__device__ __half g_Kl[(size_t)ROWS * DD];

__device__ __forceinline__ uint32_t smem_u32(const void* p) {
    uint32_t a;
    asm("{ .reg .u64 t; cvta.to.shared.u64 t, %1; cvt.u32.u64 %0, t; }" : "=r"(a) : "l"(p));
    return a;
}

#define LDMX4(r0, r1, r2, r3, addr) \
    asm volatile("ldmatrix.sync.aligned.m8n8.x4.shared.b16 {%0,%1,%2,%3}, [%4];" \
                 : "=r"(r0), "=r"(r1), "=r"(r2), "=r"(r3) : "r"(addr))

#define MMAH16816(c, a, b0, b1) \
    asm volatile("mma.sync.aligned.m16n8k16.row.col.f32.f16.f16.f32 " \
                 "{%0,%1,%2,%3}, {%4,%5,%6,%7}, {%8,%9}, {%0,%1,%2,%3};" \
                 : "+f"((c)[0]), "+f"((c)[1]), "+f"((c)[2]), "+f"((c)[3]) \
                 : "r"((a)[0]), "r"((a)[1]), "r"((a)[2]), "r"((a)[3]), \
                   "r"(b0), "r"(b1))

#define CP16(dst, src) \
    asm volatile("cp.async.cg.shared.global [%0], [%1], 16;" :: "r"(dst), "l"(src))
#define CP_COMMIT() asm volatile("cp.async.commit_group;" ::: "memory")
#define CP_WAIT0()  asm volatile("cp.async.wait_group 0;" ::: "memory")

__device__ __forceinline__ void decomp2h_store(__half* hp, __half* lp,
                                               long long off, float x, float y) {
    __half hx = __float2half(x);
    __half hy = __float2half(y);
    *(__half2*)(hp + off) = __halves2half2(hx, hy);
    *(__half2*)(lp + off) = __halves2half2(__float2half(x - __half2float(hx)),
                                           __float2half(y - __half2float(hy)));
}

// ===================== LayerNorm fused with fp16 hi/lo decompose =================
__global__ void ln_fused_kernel(const float* __restrict__ x,
                                const float* __restrict__ g,
                                const float* __restrict__ b,
                                float* __restrict__ out,          // may be null
                                __half* __restrict__ oh,
                                __half* __restrict__ ol) {        // ol may be null
    __shared__ float xs[DD];
    __shared__ float red[256];
    const int row = blockIdx.x;
    const int tid = threadIdx.x;
    const float* xr = x + (long long)row * DD;

    float s = 0.f;
    for (int i = tid; i < DD; i += 256) { float t = xr[i]; xs[i] = t; s += t; }
    red[tid] = s; __syncthreads();
    for (int o = 128; o > 0; o >>= 1) { if (tid < o) red[tid] += red[tid + o]; __syncthreads(); }
    const float mean = red[0] * (1.f / DD);
    __syncthreads();

    float v = 0.f;
    for (int i = tid; i < DD; i += 256) { float d = xs[i] - mean; v += d * d; }
    red[tid] = v; __syncthreads();
    for (int o = 128; o > 0; o >>= 1) { if (tid < o) red[tid] += red[tid + o]; __syncthreads(); }
    const float rstd = rsqrtf(red[0] * (1.f / DD) + 1e-5f);

    const long long base = (long long)row * DD;
    for (int i = tid * 2; i < DD; i += 512) {
        float a0 = (xs[i] - mean) * rstd * g[i] + b[i];
        float a1 = (xs[i + 1] - mean) * rstd * g[i + 1] + b[i + 1];
        if (out) *(float2*)(out + base + i) = make_float2(a0, a1);
        if (ol) decomp2h_store(oh, ol, base + i, a0, a1);
        else *(__half2*)(oh + base + i) = __halves2half2(__float2half(a0), __float2half(a1));
    }
}

// ===================== softmax in place + SINGLE fp16 weights ====================
__global__ void softmax_kernel(float* __restrict__ w,
                               __half* __restrict__ oh) {
    __shared__ float sc[SS_];
    __shared__ float red[256];
    const int qi = blockIdx.x, h = blockIdx.y, b = blockIdx.z;
    const int tid = threadIdx.x;
    const long long rbase = ((long long)(b * HH + h) * SS_ + qi) * SS_;
    float* wrow = w + rbase;
    const int n = qi + 1;

    float lmax = -1e30f;
    for (int j = tid; j < n; j += 256) { float t = wrow[j]; sc[j] = t; lmax = fmaxf(lmax, t); }
    red[tid] = lmax; __syncthreads();
    for (int o = 128; o > 0; o >>= 1) { if (tid < o) red[tid] = fmaxf(red[tid], red[tid + o]); __syncthreads(); }
    const float gmax = red[0];
    __syncthreads();

    float lsum = 0.f;
    for (int j = tid; j < n; j += 256) { float e = expf(sc[j] - gmax); sc[j] = e; lsum += e; }
    red[tid] = lsum; __syncthreads();
    for (int o = 128; o > 0; o >>= 1) { if (tid < o) red[tid] += red[tid + o]; __syncthreads(); }
    const float inv = 1.f / red[0];
    __syncthreads();

    for (int j = tid * 2; j < SS_; j += 512) {
        float x = (j < n) ? sc[j] * inv : 0.f;
        float y = (j + 1 < n) ? sc[j + 1] * inv : 0.f;
        *(float2*)(wrow + j) = make_float2(x, y);
        *(__half2*)(oh + rbase + j) = __halves2half2(__float2half(x), __float2half(y));
    }
}

// ===================== transpose+decompose weight [K,N] -> [N,K] (fp16 hi/lo) ====
__global__ void wtrans_h2_kernel(const float* __restrict__ w,
                                 __half* __restrict__ bh,
                                 __half* __restrict__ bl,
                                 int Kdim, int Ndim) {
    __shared__ float t[32][33];
    const int k0 = blockIdx.x * 32, n0 = blockIdx.y * 32;
    const int tx = threadIdx.x & 31, ty = threadIdx.x >> 5;
#pragma unroll
    for (int i = 0; i < 32; i += 8)
        t[ty + i][tx] = w[(long long)(k0 + ty + i) * Ndim + n0 + tx];
    __syncthreads();
#pragma unroll
    for (int i = 0; i < 32; i += 8) {
        float v = t[tx][ty + i];
        long long o = (long long)(n0 + ty + i) * Kdim + k0 + tx;
        __half h = __float2half(v);
        bh[o] = h;
        bl[o] = __float2half(v - __half2float(h));
    }
}

// ===================== transpose weight [K,N] -> [N,K] (single fp16) ============
__global__ void wtrans_h_kernel(const float* __restrict__ w,
                                __half* __restrict__ bh,
                                int Kdim, int Ndim) {
    __shared__ float t[32][33];
    const int k0 = blockIdx.x * 32, n0 = blockIdx.y * 32;
    const int tx = threadIdx.x & 31, ty = threadIdx.x >> 5;
#pragma unroll
    for (int i = 0; i < 32; i += 8)
        t[ty + i][tx] = w[(long long)(k0 + ty + i) * Ndim + n0 + tx];
    __syncthreads();
#pragma unroll
    for (int i = 0; i < 32; i += 8)
        bh[(long long)(n0 + ty + i) * Kdim + k0 + tx] = __float2half(t[tx][ty + i]);
}

// ===================== transpose V [B,S,H,DH] -> [B,H,DH,S] single fp16 ==========
__global__ void vtrans_kernel(const float* __restrict__ v,
                              __half* __restrict__ bh) {
    __shared__ float t[32][33];
    const int bh_i = blockIdx.z;
    const int b = bh_i >> 4, h = bh_i & 15;
    const int s0 = blockIdx.x * 32, d0 = blockIdx.y * 32;
    const int tx = threadIdx.x & 31, ty = threadIdx.x >> 5;
#pragma unroll
    for (int i = 0; i < 32; i += 8)
        t[ty + i][tx] = v[(((long long)b * SS_ + s0 + ty + i) * HH + h) * DH_ + d0 + tx];
    __syncthreads();
#pragma unroll
    for (int i = 0; i < 32; i += 8) {
        long long o = ((long long)bh_i * DH_ + d0 + ty + i) * SS_ + s0 + tx;
        bh[o] = __float2half(t[tx][ty + i]);
    }
}

// ===================== fp16x3 GEMM (A hi/lo x B hi/lo, 3 passes) ================
// 128x128 CTA, BK=32, 2-stage, 2 CTA/SM, 8 warps of 64x32. (q/k proj, scores)
// act: 0 none, 2 rope->Oh/Ol ; causal: 0 none, 1 skip blocks col0>row0+127
#define SA 40
#define TILEB (128 * SA * 2)
#define STAGEB (4 * TILEB)
#define GSMEM (2 * STAGEB)

__global__ __launch_bounds__(256, 2) void mma_gemm3(
        const __half* __restrict__ Ah, const __half* __restrict__ Al,
        int lda, long long sAb, long long sAhS,
        const __half* __restrict__ Bh, const __half* __restrict__ Bl,
        int ldb, long long sBb, long long sBhS,
        float* __restrict__ C,
        __half* __restrict__ Oh, __half* __restrict__ Ol,
        int ldc, long long sCb, long long sCh,
        const int* __restrict__ pos,
        int K, int Hb, int act, int causal) {
    extern __shared__ char dsm[];

    const int row0 = blockIdx.y * 128;
    const int col0 = blockIdx.x * 128;
    if (causal == 1 && col0 > row0 + 127) return;

    const int tid = threadIdx.x;
    const int warp = tid >> 5, lane = tid & 31;
    const int wm = warp >> 2, wn = warp & 3;

    const int bz = blockIdx.z;
    const int b = bz / Hb, hh = bz % Hb;
    Ah += b * sAb + hh * sAhS;
    Al += b * sAb + hh * sAhS;
    Bh += b * sBb + hh * sBhS;
    Bl += b * sBb + hh * sBhS;
    const long long cOff = b * sCb + hh * sCh;
    if (C)  C += cOff;
    if (Oh) { Oh += cOff; Ol += cOff; }

    const uint32_t u0 = smem_u32(dsm);

    float acc[4][4][4] = {};

    const int lr0 = tid >> 2, lc = (tid & 3) * 8;
    const int a_r = lane & 15, a_c = (lane >> 4) * 8;
    const int b_r = ((lane >> 4) << 3) + (lane & 7), b_c = ((lane >> 3) & 1) * 8;

    const int nch = K / 32;

    auto load_chunk = [&](int ch, int st) {
        const int kb = ch * 32;
        const uint32_t base = u0 + st * STAGEB;
#pragma unroll
        for (int p = 0; p < 2; p++) {
            const int r = lr0 + p * 64;
            const long long ga = (long long)(row0 + r) * lda + kb + lc;
            const long long gb = (long long)(col0 + r) * ldb + kb + lc;
            const uint32_t so = (uint32_t)(r * SA + lc) * 2;
            CP16(base + so,             Ah + ga);
            CP16(base + TILEB + so,     Al + ga);
            CP16(base + 2 * TILEB + so, Bh + gb);
            CP16(base + 3 * TILEB + so, Bl + gb);
        }
    };

    load_chunk(0, 0);
    CP_COMMIT();

    for (int ch = 0; ch < nch; ch++) {
        CP_WAIT0();
        __syncthreads();
        if (ch + 1 < nch) { load_chunk(ch + 1, (ch + 1) & 1); CP_COMMIT(); }

        const uint32_t base = u0 + (ch & 1) * STAGEB;
        const uint32_t uAh = base, uAl = base + TILEB;
        const uint32_t uBh = base + 2 * TILEB, uBl = base + 3 * TILEB;

#pragma unroll
        for (int ks = 0; ks < 2; ks++) {
            const int kc = ks * 16;
            uint32_t af[4][4], fbh[2][4], fbl[2][4];
#pragma unroll
            for (int nb = 0; nb < 2; nb++) {
                const uint32_t off = (uint32_t)((wn * 32 + nb * 16 + b_r) * SA + kc + b_c) * 2;
                LDMX4(fbh[nb][0], fbh[nb][1], fbh[nb][2], fbh[nb][3], uBh + off);
                LDMX4(fbl[nb][0], fbl[nb][1], fbl[nb][2], fbl[nb][3], uBl + off);
            }
#pragma unroll
            for (int mi = 0; mi < 4; mi++) {
                const uint32_t off = (uint32_t)((wm * 64 + mi * 16 + a_r) * SA + kc + a_c) * 2;
                LDMX4(af[mi][0], af[mi][1], af[mi][2], af[mi][3], uAh + off);
            }
#pragma unroll
            for (int mi = 0; mi < 4; mi++)
#pragma unroll
                for (int ni = 0; ni < 4; ni++) {
                    MMAH16816(acc[mi][ni], af[mi], fbh[ni >> 1][(ni & 1) * 2], fbh[ni >> 1][(ni & 1) * 2 + 1]);
                    MMAH16816(acc[mi][ni], af[mi], fbl[ni >> 1][(ni & 1) * 2], fbl[ni >> 1][(ni & 1) * 2 + 1]);
                }
#pragma unroll
            for (int mi = 0; mi < 4; mi++) {
                const uint32_t off = (uint32_t)((wm * 64 + mi * 16 + a_r) * SA + kc + a_c) * 2;
                LDMX4(af[mi][0], af[mi][1], af[mi][2], af[mi][3], uAl + off);
            }
#pragma unroll
            for (int mi = 0; mi < 4; mi++)
#pragma unroll
                for (int ni = 0; ni < 4; ni++)
                    MMAH16816(acc[mi][ni], af[mi], fbh[ni >> 1][(ni & 1) * 2], fbh[ni >> 1][(ni & 1) * 2 + 1]);
        }
        __syncthreads();
    }

    // epilogue
#pragma unroll
    for (int mi = 0; mi < 4; mi++) {
#pragma unroll
        for (int ni = 0; ni < 4; ni++) {
#pragma unroll
            for (int half = 0; half < 2; half++) {
                const long long r = row0 + wm * 64 + mi * 16 + (lane >> 2) + half * 8;
                const int cc = col0 + wn * 32 + ni * 8 + (lane & 3) * 2;
                float x = acc[mi][ni][half * 2];
                float y = acc[mi][ni][half * 2 + 1];
                if (act == 2) {
                    const int i = (cc & (DH_ - 1)) >> 1;
                    const float ang = (float)pos[r] * exp10f(-(float)i * (1.f / 16.f));
                    const float sn = sinf(ang), cs = cosf(ang);
                    const float nx = x * cs - y * sn;
                    y = y * cs + x * sn;
                    x = nx;
                }
                if (C) *(float2*)(C + r * ldc + cc) = make_float2(x, y);
                if (Oh) decomp2h_store(Oh, Ol, r * ldc + cc, x, y);
            }
        }
    }
}

// ===================== fp16 1/2-pass GEMM, BK=64, 2-stage, 2 CTA/SM =============
// A hi/lo (Al optional -> 1-pass), B single fp16. Batched + causal=2 K-limit.
// act: 1 gelu. Output: fp32 C and/or fp16 Oh (hi/lo if Ol, single if not).
#define SAH 72
#define HTILE (128 * SAH * 2)        // 18432
#define STAGEB_H (3 * HTILE)         // 55296
#define GSMEM_H (2 * STAGEB_H)       // 110592

__global__ __launch_bounds__(256, 2) void mma_gemm_h(
        const __half* __restrict__ Ah, const __half* __restrict__ Al,
        int lda, long long sAb, long long sAhS,
        const __half* __restrict__ Bh,
        int ldb, long long sBb, long long sBhS,
        float* __restrict__ C,
        __half* __restrict__ Oh, __half* __restrict__ Ol,
        int ldc, long long sCb, long long sCh,
        const float* __restrict__ bias,
        const float* __restrict__ res, int ldr,
        int K, int Hb, int act, int causal) {
    extern __shared__ char dsm[];

    const int row0 = blockIdx.y * 128;
    const int col0 = blockIdx.x * 128;

    const int tid = threadIdx.x;
    const int warp = tid >> 5, lane = tid & 31;
    const int wm = warp >> 2, wn = warp & 3;

    const int bz = blockIdx.z;
    const int b = bz / Hb, hh = bz % Hb;
    Ah += b * sAb + hh * sAhS;
    if (Al) Al += b * sAb + hh * sAhS;
    Bh += b * sBb + hh * sBhS;
    const long long cOff = b * sCb + hh * sCh;
    if (C)  C += cOff;
    if (Oh) { Oh += cOff; if (Ol) Ol += cOff; }

    const uint32_t u0 = smem_u32(dsm);

    float acc[4][4][4] = {};

    const int lr0 = tid >> 3, lc = (tid & 7) * 8;   // 32 rows per pass, 64 cols
    const int a_r = lane & 15, a_c = (lane >> 4) * 8;
    const int b_r = ((lane >> 4) << 3) + (lane & 7), b_c = ((lane >> 3) & 1) * 8;

    int nch = K / 64;
    if (causal == 2) { int lim = (row0 + 128) / 64; if (lim < nch) nch = lim; }

    auto load_chunk = [&](int ch, int st) {
        const int kb = ch * 64;
        const uint32_t base = u0 + st * STAGEB_H;
#pragma unroll
        for (int p = 0; p < 4; p++) {
            const int r = lr0 + p * 32;
            const long long ga = (long long)(row0 + r) * lda + kb + lc;
            const long long gb = (long long)(col0 + r) * ldb + kb + lc;
            const uint32_t so = (uint32_t)(r * SAH + lc) * 2;
            CP16(base + so, Ah + ga);
            if (Al) CP16(base + HTILE + so, Al + ga);
            CP16(base + 2 * HTILE + so, Bh + gb);
        }
    };

    load_chunk(0, 0);
    CP_COMMIT();

    for (int ch = 0; ch < nch; ch++) {
        CP_WAIT0();
        __syncthreads();
        if (ch + 1 < nch) { load_chunk(ch + 1, (ch + 1) & 1); CP_COMMIT(); }

        const uint32_t base = u0 + (ch & 1) * STAGEB_H;
        const uint32_t uAh = base, uAl = base + HTILE;
        const uint32_t uBh = base + 2 * HTILE;

#pragma unroll
        for (int ks = 0; ks < 4; ks++) {
            const int kc = ks * 16;
            uint32_t af[4][4], fbh[2][4];
#pragma unroll
            for (int nb = 0; nb < 2; nb++) {
                const uint32_t off = (uint32_t)((wn * 32 + nb * 16 + b_r) * SAH + kc + b_c) * 2;
                LDMX4(fbh[nb][0], fbh[nb][1], fbh[nb][2], fbh[nb][3], uBh + off);
            }
#pragma unroll
            for (int mi = 0; mi < 4; mi++) {
                const uint32_t off = (uint32_t)((wm * 64 + mi * 16 + a_r) * SAH + kc + a_c) * 2;
                LDMX4(af[mi][0], af[mi][1], af[mi][2], af[mi][3], uAh + off);
            }
#pragma unroll
            for (int mi = 0; mi < 4; mi++)
#pragma unroll
                for (int ni = 0; ni < 4; ni++)
                    MMAH16816(acc[mi][ni], af[mi], fbh[ni >> 1][(ni & 1) * 2], fbh[ni >> 1][(ni & 1) * 2 + 1]);
            if (Al) {
#pragma unroll
                for (int mi = 0; mi < 4; mi++) {
                    const uint32_t off = (uint32_t)((wm * 64 + mi * 16 + a_r) * SAH + kc + a_c) * 2;
                    LDMX4(af[mi][0], af[mi][1], af[mi][2], af[mi][3], uAl + off);
                }
#pragma unroll
                for (int mi = 0; mi < 4; mi++)
#pragma unroll
                    for (int ni = 0; ni < 4; ni++)
                        MMAH16816(acc[mi][ni], af[mi], fbh[ni >> 1][(ni & 1) * 2], fbh[ni >> 1][(ni & 1) * 2 + 1]);
            }
        }
        __syncthreads();
    }

    // epilogue
#pragma unroll
    for (int mi = 0; mi < 4; mi++) {
#pragma unroll
        for (int ni = 0; ni < 4; ni++) {
#pragma unroll
            for (int half = 0; half < 2; half++) {
                const long long r = row0 + wm * 64 + mi * 16 + (lane >> 2) + half * 8;
                const int cc = col0 + wn * 32 + ni * 8 + (lane & 3) * 2;
                float x = acc[mi][ni][half * 2];
                float y = acc[mi][ni][half * 2 + 1];
                if (bias) { x += bias[cc]; y += bias[cc + 1]; }
                if (act == 1) {
                    x = 0.5f * x * (1.f + erff(x * 0.70710678118654752f));
                    y = 0.5f * y * (1.f + erff(y * 0.70710678118654752f));
                }
                if (res) { x += res[r * ldr + cc]; y += res[r * ldr + cc + 1]; }
                if (C) *(float2*)(C + r * ldc + cc) = make_float2(x, y);
                if (Oh) {
                    if (Ol) decomp2h_store(Oh, Ol, r * ldc + cc, x, y);
                    else *(__half2*)(Oh + r * ldc + cc) =
                             __halves2half2(__float2half(x), __float2half(y));
                }
            }
        }
    }
}

// ===================== host launch =====================
extern "C" void kernel_launch(void* const* d_in, const int* in_sizes, int n_in,
                              void* d_out, int out_size) {
    const float* hidden  = (const float*)d_in[0];
    const int*   pos     = (const int*)  d_in[1];
    const float* wq      = (const float*)d_in[2];
    const float* wk      = (const float*)d_in[3];
    const float* wv      = (const float*)d_in[4];
    const float* wo      = (const float*)d_in[5];
    const float* ln1_g   = (const float*)d_in[6];
    const float* ln1_b   = (const float*)d_in[7];
    const float* ln2_g   = (const float*)d_in[8];
    const float* ln2_b   = (const float*)d_in[9];
    const float* fc_in_w = (const float*)d_in[10];
    const float* fc_in_b = (const float*)d_in[11];
    const float* fc_out_w= (const float*)d_in[12];
    const float* fc_out_b= (const float*)d_in[13];

    float* out0 = (float*)d_out;                               // [B,S,D]
    float* out1 = out0 + (long long)BB * SS_ * DD;             // [B,H,S,S]

    float *h, *v, *res;
    __half *Ah, *Al, *Bh, *Bl, *Ch, *Cl, *Kh, *Kl;
    cudaGetSymbolAddress((void**)&h,   g_h);
    cudaGetSymbolAddress((void**)&v,   g_v);
    cudaGetSymbolAddress((void**)&res, g_res);
    cudaGetSymbolAddress((void**)&Ah,  g_Ah);
    cudaGetSymbolAddress((void**)&Al,  g_Al);
    cudaGetSymbolAddress((void**)&Bh,  g_Bh);
    cudaGetSymbolAddress((void**)&Bl,  g_Bl);
    cudaGetSymbolAddress((void**)&Ch,  g_Ch);
    cudaGetSymbolAddress((void**)&Cl,  g_Cl);
    cudaGetSymbolAddress((void**)&Kh,  g_Kh);
    cudaGetSymbolAddress((void**)&Kl,  g_Kl);

    cudaFuncSetAttribute(mma_gemm3,  cudaFuncAttributeMaxDynamicSharedMemorySize, GSMEM);
    cudaFuncSetAttribute(mma_gemm_h, cudaFuncAttributeMaxDynamicSharedMemorySize, GSMEM_H);

    // 1. LN1 -> fp16 hi/lo (q/k path needs hi/lo; v proj uses hi only)
    ln_fused_kernel<<<ROWS, 256>>>(hidden, ln1_g, ln1_b, nullptr, Ah, Al);

    // 2. QKV: q,k via fp16x3 + fused RoPE -> hi/lo; v via fp16 1-pass -> fp32
    dim3 gQ(DD / 128, ROWS / 128, 1);
    dim3 gW(DD / 32, DD / 32);
    wtrans_h2_kernel<<<gW, 256>>>(wq, Bh, Bl, DD, DD);
    mma_gemm3<<<gQ, 256, GSMEM>>>(Ah, Al, DD, 0, 0, Bh, Bl, DD, 0, 0,
                                  nullptr, Ch, Cl, DD, 0, 0, pos, DD, 1, 2, 0);
    wtrans_h2_kernel<<<gW, 256>>>(wk, Bh, Bl, DD, DD);
    mma_gemm3<<<gQ, 256, GSMEM>>>(Ah, Al, DD, 0, 0, Bh, Bl, DD, 0, 0,
                                  nullptr, Kh, Kl, DD, 0, 0, pos, DD, 1, 2, 0);
    wtrans_h_kernel<<<gW, 256>>>(wv, Bh, DD, DD);
    mma_gemm_h<<<gQ, 256, GSMEM_H>>>(Ah, nullptr, DD, 0, 0, Bh, DD, 0, 0,
                                     v, nullptr, nullptr, DD, 0, 0,
                                     nullptr, nullptr, 0, DD, 1, 0, 0);

    // 3. scores = q @ k^T (causal blocks) -> out1 fp32 (fp16x3)
    {
        dim3 gS(SS_ / 128, SS_ / 128, BB * HH);
        mma_gemm3<<<gS, 256, GSMEM>>>(
            Ch, Cl, DD, (long long)SS_ * DD, DH_,
            Kh, Kl, DD, (long long)SS_ * DD, DH_,
            out1, nullptr, nullptr, SS_, (long long)HH * SS_ * SS_, (long long)SS_ * SS_,
            nullptr, DH_, HH, 0, 1);
    }

    // 4. softmax in place + single fp16 weights -> Ah
    {
        dim3 gA(SS_, HH, BB);
        softmax_kernel<<<gA, 256>>>(out1, Ah);
    }

    // 5. v^T -> single fp16 Bh; ctx = weights @ v  [fp16 1-pass]; ctx stored single -> Ch
    {
        dim3 gVT(SS_ / 32, DH_ / 32, BB * HH);
        vtrans_kernel<<<gVT, 256>>>(v, Bh);
        dim3 gV(DH_ / 128, SS_ / 128, BB * HH);
        mma_gemm_h<<<gV, 256, GSMEM_H>>>(
            Ah, nullptr, SS_, (long long)HH * SS_ * SS_, (long long)SS_ * SS_,
            Bh, SS_, (long long)HH * DH_ * SS_, (long long)DH_ * SS_,
            nullptr, Ch, nullptr, DD, (long long)SS_ * DD, DH_,
            nullptr, nullptr, 0, SS_, HH, 0, 2);
    }

    // 6. res = ctx @ wo + hidden (fp32)  [fp16 1-pass]
    wtrans_h_kernel<<<gW, 256>>>(wo, Bh, DD, DD);
    mma_gemm_h<<<gQ, 256, GSMEM_H>>>(Ch, nullptr, DD, 0, 0, Bh, DD, 0, 0,
                                     res, nullptr, nullptr, DD, 0, 0,
                                     nullptr, hidden, DD, DD, 1, 0, 0);

    // 7. LN2 -> h fp32 + single fp16 Ah
    ln_fused_kernel<<<ROWS, 256>>>(res, ln2_g, ln2_b, h, Ah, nullptr);

    // 8. ffn = gelu(h2 @ fc_in + b) -> single fp16 Ch  [fp16 1-pass]
    {
        dim3 gW1(DD / 32, FF_ / 32);
        wtrans_h_kernel<<<gW1, 256>>>(fc_in_w, Bh, DD, FF_);
        dim3 gF1(FF_ / 128, ROWS / 128, 1);
        mma_gemm_h<<<gF1, 256, GSMEM_H>>>(Ah, nullptr, DD, 0, 0, Bh, DD, 0, 0,
                                          nullptr, Ch, nullptr, FF_, 0, 0,
                                          fc_in_b, nullptr, 0, DD, 1, 1, 0);
    }

    // 9. out0 = ffn @ fc_out + b + h2  [fp16 1-pass]
    {
        dim3 gW2(FF_ / 32, DD / 32);
        wtrans_h_kernel<<<gW2, 256>>>(fc_out_w, Bh, FF_, DD);
        dim3 gF2(DD / 128, ROWS / 128, 1);
        mma_gemm_h<<<gF2, 256, GSMEM_H>>>(Ch, nullptr, FF_, 0, 0, Bh, FF_, 0, 0,
                                          out0, nullptr, nullptr, DD, 0, 0,
                                          fc_out_b, h, DD, FF_, 1, 0, 0);
    }
}